// round 2
// baseline (speedup 1.0000x reference)
#include <cuda_runtime.h>

#define Bv 2
#define CINv 64
#define COUTv 64
#define Hv 192
#define Wv 192
#define Gv 2
#define KKv 9
#define CGv 32
#define HWv (Hv*Wv)

// ---------------- scratch (__device__ globals; no runtime alloc) ----------------
__device__ float g_nhwc[Bv*Hv*Wv*CINv];        // input transposed to NHWC
__device__ float g_py  [Bv*Gv*KKv*HWv];        // absolute sample y
__device__ float g_px  [Bv*Gv*KKv*HWv];        // absolute sample x
__device__ float g_dm  [Bv*Gv*KKv*HWv];        // modulation mask (post-sigmoid)
__device__ float g_wt  [Gv*KKv*CGv*COUTv];     // main weight transposed [g][k][c][o]
__device__ float g_wk  [KKv*64*28];            // sem+m2 weights transposed [k][c][oc(28)]
__device__ float4 g_S  [Bv*Gv*KKv*8*HWv];      // sampled+modulated im2col: [(b,g,k,c4)][hw] -> 4 ch

// ---------------- f32x2 packed helpers ----------------
__device__ __forceinline__ unsigned long long pack2(float lo, float hi) {
    unsigned long long r;
    asm("mov.b64 %0, {%1, %2};" : "=l"(r) : "f"(lo), "f"(hi));
    return r;
}
__device__ __forceinline__ void ffma2(unsigned long long &d,
                                      unsigned long long a,
                                      unsigned long long b) {
    asm("fma.rn.f32x2 %0, %1, %2, %0;" : "+l"(d) : "l"(a), "l"(b));
}
__device__ __forceinline__ float2 unpack2(unsigned long long v) {
    float2 r;
    asm("mov.b64 {%0, %1}, %2;" : "=f"(r.x), "=f"(r.y) : "l"(v));
    return r;
}

// ---------------- kernel: NCHW -> NHWC transpose (smem tiled) ----------------
__global__ void k_transpose(const float* __restrict__ in) {
    __shared__ float tile[64][33];
    int b  = blockIdx.z;
    int h  = blockIdx.y;
    int w0 = blockIdx.x * 32;
    int tw = threadIdx.x & 31;
    int tc = threadIdx.x >> 5;
    #pragma unroll
    for (int c = tc; c < 64; c += 8)
        tile[c][tw] = in[(((size_t)b*CINv + c)*Hv + h)*Wv + w0 + tw];
    __syncthreads();
    int oc = threadIdx.x & 63;
    #pragma unroll
    for (int j = threadIdx.x >> 6; j < 32; j += 4)
        g_nhwc[(((size_t)b*Hv + h)*Wv + w0 + j)*CINv + oc] = tile[oc][j];
}

// ---------------- kernel: transpose weights into gather-friendly layouts ----------------
__global__ void k_prep(const float* __restrict__ weight,
                       const float* __restrict__ sem_w,
                       const float* __restrict__ m2_w) {
    int i = blockIdx.x * 256 + threadIdx.x;
    if (i < Gv*KKv*CGv*COUTv) {
        int o = i & 63;
        int c = (i >> 6) & 31;
        int k = (i >> 11) % KKv;
        int g = i / (2048 * KKv);
        g_wt[i] = weight[((size_t)o*CINv + g*CGv + c)*KKv + k];
    }
    if (i < KKv*64*28) {
        int oc = i % 28;
        int c  = (i / 28) % 64;
        int k  = i / (28 * 64);
        float v = 0.f;
        if (oc < 18)      v = sem_w[((size_t)oc*64 + c)*KKv + k];
        else if (oc < 27) v = m2_w[((size_t)(oc-18)*64 + c)*KKv + k];
        g_wk[i] = v;
    }
}

// ---------------- kernel: offsets + modulation masks + update_mask ----------------
__global__ void __launch_bounds__(128)
k_offsets(const float* __restrict__ mask,
          const float* __restrict__ sem_b,
          const float* __restrict__ reg_w, const float* __restrict__ reg_b,
          const float* __restrict__ m1_w,  const float* __restrict__ m1_b,
          const float* __restrict__ m2_b,
          float* __restrict__ out) {
    extern __shared__ float wsm[];   // [k][c][28] = 16128 floats
    for (int i = threadIdx.x * 4; i < KKv*64*28; i += 128 * 4)
        *(float4*)(wsm + i) = *(const float4*)(g_wk + i);
    __syncthreads();

    int pix = blockIdx.x * 128 + threadIdx.x;
    int b  = pix / HWv;
    int hw = pix % HWv;
    int h  = hw / Wv;
    int w  = hw % Wv;

    unsigned long long acc[14];
    #pragma unroll
    for (int j = 0; j < 14; j++) {
        int a = 2*j, c2 = 2*j + 1;
        float lo = (a  < 18) ? sem_b[a]  : ((a  < 27) ? m2_b[a  - 18] : 0.f);
        float hi = (c2 < 18) ? sem_b[c2] : ((c2 < 27) ? m2_b[c2 - 18] : 0.f);
        acc[j] = pack2(lo, hi);
    }

    #pragma unroll 1
    for (int k = 0; k < 9; k++) {
        int yy = h + k / 3 - 1, xx = w + k % 3 - 1;
        if ((unsigned)yy < Hv && (unsigned)xx < Wv) {
            const float4* p = (const float4*)(g_nhwc + (((size_t)b*Hv + yy)*Wv + xx)*64);
            const float* wrow = wsm + k * 64 * 28;
            #pragma unroll 2
            for (int c4 = 0; c4 < 16; c4++) {
                float4 v = p[c4];
                float sarr[4] = {v.x, v.y, v.z, v.w};
                #pragma unroll
                for (int e = 0; e < 4; e++) {
                    unsigned long long s2 = pack2(sarr[e], sarr[e]);
                    const ulonglong2* wp = (const ulonglong2*)(wrow + (c4*4 + e) * 28);
                    #pragma unroll
                    for (int j2 = 0; j2 < 7; j2++) {
                        ulonglong2 q = wp[j2];
                        ffma2(acc[2*j2],     s2, q.x);
                        ffma2(acc[2*j2 + 1], s2, q.y);
                    }
                }
            }
        }
    }
    float res[28];
    #pragma unroll
    for (int j = 0; j < 14; j++) { float2 t = unpack2(acc[j]); res[2*j] = t.x; res[2*j+1] = t.y; }

    float mv[9];
    #pragma unroll
    for (int k = 0; k < 9; k++) {
        int yy = h + k / 3 - 1, xx = w + k % 3 - 1;
        mv[k] = ((unsigned)yy < Hv && (unsigned)xx < Wv) ? mask[(size_t)b*HWv + yy*Wv + xx] : 0.f;
    }
    float ro[18];
    #pragma unroll
    for (int i = 0; i < 18; i++) {
        float s = reg_b[i];
        #pragma unroll
        for (int k = 0; k < 9; k++) s += mv[k] * __ldg(&reg_w[i*9 + k]);
        ro[i] = s;
    }
    float d1[9];
    #pragma unroll
    for (int j = 0; j < 9; j++) {
        float s = m1_b[j];
        #pragma unroll
        for (int k = 0; k < 9; k++) s += mv[k] * __ldg(&m1_w[j*9 + k]);
        d1[j] = 1.f / (1.f + __expf(-s));
    }

    const float* mb = mask + (size_t)b * HWv;
    float umsum = 0.f;
    #pragma unroll
    for (int g = 0; g < 2; g++) {
        #pragma unroll
        for (int k = 0; k < 9; k++) {
            float dy = g ? res[2*k]     : ro[2*k];
            float dx = g ? res[2*k + 1] : ro[2*k + 1];
            float py = dy + (float)h + (float)(k / 3 - 1);
            float px = dx + (float)w + (float)(k % 3 - 1);
            int idx = (((b*2 + g)*9) + k) * HWv + hw;
            g_py[idx] = py;
            g_px[idx] = px;
            g_dm[idx] = g ? (1.f / (1.f + __expf(-res[18 + k]))) : d1[k];

            float y0f = floorf(py), x0f = floorf(px);
            int y0 = (int)y0f, x0 = (int)x0f;
            float ly = py - y0f, lx = px - x0f;
            float v00 = ((unsigned)y0     < Hv && (unsigned)x0     < Wv) ? mb[y0*Wv + x0]         : 0.f;
            float v01 = ((unsigned)y0     < Hv && (unsigned)(x0+1) < Wv) ? mb[y0*Wv + x0 + 1]     : 0.f;
            float v10 = ((unsigned)(y0+1) < Hv && (unsigned)x0     < Wv) ? mb[(y0+1)*Wv + x0]     : 0.f;
            float v11 = ((unsigned)(y0+1) < Hv && (unsigned)(x0+1) < Wv) ? mb[(y0+1)*Wv + x0 + 1] : 0.f;
            umsum += (v00*(1.f-ly) + v10*ly)*(1.f-lx) + (v01*(1.f-ly) + v11*ly)*lx;
        }
    }
    out[(size_t)Bv*COUTv*HWv + (size_t)b*HWv + hw] = fminf(fmaxf(64.f * umsum, 0.f), 1.f);
}

// ---------------- kernel: coalesced bilinear gather -> im2col S ----------------
// block = 128 thr (4 warps), handles 32 pixels; warp lanes = channels (coalesced
// corner reads: 1 cache line each). SMEM transpose, then float4 writes with
// lanes = consecutive pixels (coalesced).
__global__ void __launch_bounds__(128)
k_gather() {
    __shared__ float sm[4][32][33];
    int warp = threadIdx.x >> 5;
    int l    = threadIdx.x & 31;           // lane = channel within group
    int pix0 = blockIdx.x * 32;
    int b    = pix0 / HWv;
    int hw0  = pix0 % HWv;

    for (int kk = warp; kk < 18; kk += 4) {
        int g = kk / 9;
        int idx = kk * HWv + (size_t)b * (18 * HWv) + hw0;  // ((b*2+g)*9+k)*HW + hw0
        // note: ((b*2+g)*9+k) == b*18 + kk
        float py = g_py[idx + l];
        float px = g_px[idx + l];
        float dm = g_dm[idx + l];
        const float* xb = g_nhwc + ((size_t)b * HWv) * 64 + g * 32 + l;

        #pragma unroll 4
        for (int p = 0; p < 32; p++) {
            float pyp = __shfl_sync(0xffffffffu, py, p);
            float pxp = __shfl_sync(0xffffffffu, px, p);
            float dmp = __shfl_sync(0xffffffffu, dm, p);
            float y0f = floorf(pyp), x0f = floorf(pxp);
            int y0 = (int)y0f, x0 = (int)x0f;
            float ly = pyp - y0f, lx = pxp - x0f;
            bool vy0 = (unsigned)y0       < Hv;
            bool vy1 = (unsigned)(y0 + 1) < Hv;
            bool vx0 = (unsigned)x0       < Wv;
            bool vx1 = (unsigned)(x0 + 1) < Wv;
            float v00 = 0.f, v01 = 0.f, v10 = 0.f, v11 = 0.f;
            if (vy0 && vx0) v00 = xb[(y0*Wv + x0) * 64];
            if (vy0 && vx1) v01 = xb[(y0*Wv + x0 + 1) * 64];
            if (vy1 && vx0) v10 = xb[((y0+1)*Wv + x0) * 64];
            if (vy1 && vx1) v11 = xb[((y0+1)*Wv + x0 + 1) * 64];
            float val = ((v00*(1.f-ly) + v10*ly)*(1.f-lx)
                       + (v01*(1.f-ly) + v11*ly)*lx) * dmp;
            sm[warp][l][p] = val;
        }
        __syncwarp();
        int slabbase = (b * 18 + kk) * 8;
        #pragma unroll
        for (int q = 0; q < 8; q++) {
            float4 v;
            v.x = sm[warp][4*q + 0][l];
            v.y = sm[warp][4*q + 1][l];
            v.z = sm[warp][4*q + 2][l];
            v.w = sm[warp][4*q + 3][l];
            g_S[(size_t)(slabbase + q) * HWv + hw0 + l] = v;
        }
        __syncwarp();
    }
}

// ---------------- kernel: register-blocked GEMM out = W(64x576) * S(576xHW) ----------------
// block 256 thr: tile 64o x 128px, thread micro-tile 4o x 8px (16 f32x2 accs).
__global__ void __launch_bounds__(256)
k_gemm(const float* __restrict__ bias, float* __restrict__ out) {
    __shared__ float Wsm[32 * 64];
    __shared__ float Ssm[32 * 128];
    int t   = threadIdx.x;
    int b   = blockIdx.x / (HWv / 128);
    int hw0 = (blockIdx.x % (HWv / 128)) * 128;
    int po  = (t >> 4) << 2;     // output-channel base (0..60)
    int pp  = (t & 15) << 3;     // pixel base (0..120)

    unsigned long long acc[16];
    #pragma unroll
    for (int j = 0; j < 16; j++) acc[j] = 0ull;

    #pragma unroll 1
    for (int kk = 0; kk < 18; kk++) {
        __syncthreads();
        const float4* wsrc = (const float4*)(g_wt + kk * 2048);
        ((float4*)Wsm)[t]       = wsrc[t];
        ((float4*)Wsm)[t + 256] = wsrc[t + 256];
        int base = (b * 18 + kk) * 8;
        #pragma unroll
        for (int i = 0; i < 4; i++) {
            int f = t + i * 256;           // 0..1023
            int q = f >> 7, p = f & 127;
            float4 v = g_S[(size_t)(base + q) * HWv + hw0 + p];
            Ssm[(4*q + 0) * 128 + p] = v.x;
            Ssm[(4*q + 1) * 128 + p] = v.y;
            Ssm[(4*q + 2) * 128 + p] = v.z;
            Ssm[(4*q + 3) * 128 + p] = v.w;
        }
        __syncthreads();
        #pragma unroll 8
        for (int c = 0; c < 32; c++) {
            ulonglong2 s01 = *(const ulonglong2*)(Ssm + c * 128 + pp);
            ulonglong2 s23 = *(const ulonglong2*)(Ssm + c * 128 + pp + 4);
            float4 wv = *(const float4*)(Wsm + c * 64 + po);
            float wa[4] = {wv.x, wv.y, wv.z, wv.w};
            #pragma unroll
            for (int e = 0; e < 4; e++) {
                unsigned long long w2 = pack2(wa[e], wa[e]);
                ffma2(acc[e*4 + 0], w2, s01.x);
                ffma2(acc[e*4 + 1], w2, s01.y);
                ffma2(acc[e*4 + 2], w2, s23.x);
                ffma2(acc[e*4 + 3], w2, s23.y);
            }
        }
    }

    // epilogue: (acc + bias) * update_mask
    const float* umP = out + (size_t)Bv*COUTv*HWv + (size_t)b*HWv + hw0 + pp;
    float4 um0 = *(const float4*)(umP);
    float4 um1 = *(const float4*)(umP + 4);
    #pragma unroll
    for (int e = 0; e < 4; e++) {
        float bv = bias[po + e];
        float2 r0 = unpack2(acc[e*4 + 0]);
        float2 r1 = unpack2(acc[e*4 + 1]);
        float2 r2 = unpack2(acc[e*4 + 2]);
        float2 r3 = unpack2(acc[e*4 + 3]);
        float* op = out + ((size_t)b*COUTv + po + e)*HWv + hw0 + pp;
        float4 o0 = {(r0.x + bv)*um0.x, (r0.y + bv)*um0.y,
                     (r1.x + bv)*um0.z, (r1.y + bv)*um0.w};
        float4 o1 = {(r2.x + bv)*um1.x, (r2.y + bv)*um1.y,
                     (r3.x + bv)*um1.z, (r3.y + bv)*um1.w};
        *(float4*)op       = o0;
        *(float4*)(op + 4) = o1;
    }
}

// ---------------- launcher ----------------
extern "C" void kernel_launch(void* const* d_in, const int* in_sizes, int n_in,
                              void* d_out, int out_size) {
    const float* input  = (const float*)d_in[0];
    const float* mask   = (const float*)d_in[1];
    const float* weight = (const float*)d_in[2];
    const float* bias   = (const float*)d_in[3];
    const float* sem_w  = (const float*)d_in[4];
    const float* sem_b  = (const float*)d_in[5];
    const float* reg_w  = (const float*)d_in[6];
    const float* reg_b  = (const float*)d_in[7];
    const float* m1_w   = (const float*)d_in[8];
    const float* m1_b   = (const float*)d_in[9];
    const float* m2_w   = (const float*)d_in[10];
    const float* m2_b   = (const float*)d_in[11];
    float* out = (float*)d_out;

    cudaFuncSetAttribute(k_offsets, cudaFuncAttributeMaxDynamicSharedMemorySize, KKv*64*28*4);

    k_transpose<<<dim3(Wv/32, Hv, Bv), 256>>>(input);
    k_prep<<<(Gv*KKv*CGv*COUTv + 255)/256, 256>>>(weight, sem_w, m2_w);
    k_offsets<<<(Bv*HWv)/128, 128, KKv*64*28*4>>>(mask, sem_b, reg_w, reg_b,
                                                  m1_w, m1_b, m2_b, out);
    k_gather<<<(Bv*HWv)/32, 128>>>();
    k_gemm<<<(Bv*HWv)/128, 256>>>(bias, out);
}

// round 3
// speedup vs baseline: 1.2460x; 1.2460x over previous
#include <cuda_runtime.h>

#define Bv 2
#define CINv 64
#define COUTv 64
#define Hv 192
#define Wv 192
#define Gv 2
#define KKv 9
#define CGv 32
#define HWv (Hv*Wv)

// ---------------- scratch (__device__ globals; no runtime alloc) ----------------
__device__ float g_nhwc[Bv*Hv*Wv*CINv];        // input transposed to NHWC
__device__ float g_py  [Bv*Gv*KKv*HWv];        // absolute sample y
__device__ float g_px  [Bv*Gv*KKv*HWv];        // absolute sample x
__device__ float g_dm  [Bv*Gv*KKv*HWv];        // modulation mask (post-sigmoid)
__device__ float g_wt  [Gv*KKv*CGv*COUTv];     // main weight transposed [g][k][c][o]
__device__ float g_wk  [KKv*64*28];            // sem+m2 weights transposed [k][c][oc(28)]
__device__ float4 g_S  [Bv*Gv*KKv*8*HWv];      // sampled+modulated im2col: [(b,g,k,c4)][hw] -> 4 ch

// ---------------- f32x2 packed helpers ----------------
__device__ __forceinline__ unsigned long long pack2(float lo, float hi) {
    unsigned long long r;
    asm("mov.b64 %0, {%1, %2};" : "=l"(r) : "f"(lo), "f"(hi));
    return r;
}
__device__ __forceinline__ void ffma2(unsigned long long &d,
                                      unsigned long long a,
                                      unsigned long long b) {
    asm("fma.rn.f32x2 %0, %1, %2, %0;" : "+l"(d) : "l"(a), "l"(b));
}
__device__ __forceinline__ float2 unpack2(unsigned long long v) {
    float2 r;
    asm("mov.b64 {%0, %1}, %2;" : "=f"(r.x), "=f"(r.y) : "l"(v));
    return r;
}

// ---------------- kernel: NCHW -> NHWC transpose (smem tiled) ----------------
__global__ void k_transpose(const float* __restrict__ in) {
    __shared__ float tile[64][33];
    int b  = blockIdx.z;
    int h  = blockIdx.y;
    int w0 = blockIdx.x * 32;
    int tw = threadIdx.x & 31;
    int tc = threadIdx.x >> 5;
    #pragma unroll
    for (int c = tc; c < 64; c += 8)
        tile[c][tw] = in[(((size_t)b*CINv + c)*Hv + h)*Wv + w0 + tw];
    __syncthreads();
    int oc = threadIdx.x & 63;
    #pragma unroll
    for (int j = threadIdx.x >> 6; j < 32; j += 4)
        g_nhwc[(((size_t)b*Hv + h)*Wv + w0 + j)*CINv + oc] = tile[oc][j];
}

// ---------------- kernel: transpose weights into gather-friendly layouts ----------------
__global__ void k_prep(const float* __restrict__ weight,
                       const float* __restrict__ sem_w,
                       const float* __restrict__ m2_w) {
    int i = blockIdx.x * 256 + threadIdx.x;
    if (i < Gv*KKv*CGv*COUTv) {
        int o = i & 63;
        int c = (i >> 6) & 31;
        int k = (i >> 11) % KKv;
        int g = i / (2048 * KKv);
        g_wt[i] = weight[((size_t)o*CINv + g*CGv + c)*KKv + k];
    }
    if (i < KKv*64*28) {
        int oc = i % 28;
        int c  = (i / 28) % 64;
        int k  = i / (28 * 64);
        float v = 0.f;
        if (oc < 18)      v = sem_w[((size_t)oc*64 + c)*KKv + k];
        else if (oc < 27) v = m2_w[((size_t)(oc-18)*64 + c)*KKv + k];
        g_wk[i] = v;
    }
}

// ---------------- kernel: offsets + modulation masks + update_mask ----------------
__global__ void __launch_bounds__(128)
k_offsets(const float* __restrict__ mask,
          const float* __restrict__ sem_b,
          const float* __restrict__ reg_w, const float* __restrict__ reg_b,
          const float* __restrict__ m1_w,  const float* __restrict__ m1_b,
          const float* __restrict__ m2_b,
          float* __restrict__ out) {
    extern __shared__ float wsm[];   // [k][c][28] = 16128 floats
    for (int i = threadIdx.x * 4; i < KKv*64*28; i += 128 * 4)
        *(float4*)(wsm + i) = *(const float4*)(g_wk + i);
    __syncthreads();

    int pix = blockIdx.x * 128 + threadIdx.x;
    int b  = pix / HWv;
    int hw = pix % HWv;
    int h  = hw / Wv;
    int w  = hw % Wv;

    unsigned long long acc[14];
    #pragma unroll
    for (int j = 0; j < 14; j++) {
        int a = 2*j, c2 = 2*j + 1;
        float lo = (a  < 18) ? sem_b[a]  : ((a  < 27) ? m2_b[a  - 18] : 0.f);
        float hi = (c2 < 18) ? sem_b[c2] : ((c2 < 27) ? m2_b[c2 - 18] : 0.f);
        acc[j] = pack2(lo, hi);
    }

    #pragma unroll 1
    for (int k = 0; k < 9; k++) {
        int yy = h + k / 3 - 1, xx = w + k % 3 - 1;
        if ((unsigned)yy < Hv && (unsigned)xx < Wv) {
            const float4* p = (const float4*)(g_nhwc + (((size_t)b*Hv + yy)*Wv + xx)*64);
            const float* wrow = wsm + k * 64 * 28;
            #pragma unroll 2
            for (int c4 = 0; c4 < 16; c4++) {
                float4 v = p[c4];
                float sarr[4] = {v.x, v.y, v.z, v.w};
                #pragma unroll
                for (int e = 0; e < 4; e++) {
                    unsigned long long s2 = pack2(sarr[e], sarr[e]);
                    const ulonglong2* wp = (const ulonglong2*)(wrow + (c4*4 + e) * 28);
                    #pragma unroll
                    for (int j2 = 0; j2 < 7; j2++) {
                        ulonglong2 q = wp[j2];
                        ffma2(acc[2*j2],     s2, q.x);
                        ffma2(acc[2*j2 + 1], s2, q.y);
                    }
                }
            }
        }
    }
    float res[28];
    #pragma unroll
    for (int j = 0; j < 14; j++) { float2 t = unpack2(acc[j]); res[2*j] = t.x; res[2*j+1] = t.y; }

    float mv[9];
    #pragma unroll
    for (int k = 0; k < 9; k++) {
        int yy = h + k / 3 - 1, xx = w + k % 3 - 1;
        mv[k] = ((unsigned)yy < Hv && (unsigned)xx < Wv) ? mask[(size_t)b*HWv + yy*Wv + xx] : 0.f;
    }
    float ro[18];
    #pragma unroll
    for (int i = 0; i < 18; i++) {
        float s = reg_b[i];
        #pragma unroll
        for (int k = 0; k < 9; k++) s += mv[k] * __ldg(&reg_w[i*9 + k]);
        ro[i] = s;
    }
    float d1[9];
    #pragma unroll
    for (int j = 0; j < 9; j++) {
        float s = m1_b[j];
        #pragma unroll
        for (int k = 0; k < 9; k++) s += mv[k] * __ldg(&m1_w[j*9 + k]);
        d1[j] = 1.f / (1.f + __expf(-s));
    }

    const float* mb = mask + (size_t)b * HWv;
    float umsum = 0.f;
    #pragma unroll
    for (int g = 0; g < 2; g++) {
        #pragma unroll
        for (int k = 0; k < 9; k++) {
            float dy = g ? res[2*k]     : ro[2*k];
            float dx = g ? res[2*k + 1] : ro[2*k + 1];
            float py = dy + (float)h + (float)(k / 3 - 1);
            float px = dx + (float)w + (float)(k % 3 - 1);
            int idx = (((b*2 + g)*9) + k) * HWv + hw;
            g_py[idx] = py;
            g_px[idx] = px;
            g_dm[idx] = g ? (1.f / (1.f + __expf(-res[18 + k]))) : d1[k];

            float y0f = floorf(py), x0f = floorf(px);
            int y0 = (int)y0f, x0 = (int)x0f;
            float ly = py - y0f, lx = px - x0f;
            float v00 = ((unsigned)y0     < Hv && (unsigned)x0     < Wv) ? mb[y0*Wv + x0]         : 0.f;
            float v01 = ((unsigned)y0     < Hv && (unsigned)(x0+1) < Wv) ? mb[y0*Wv + x0 + 1]     : 0.f;
            float v10 = ((unsigned)(y0+1) < Hv && (unsigned)x0     < Wv) ? mb[(y0+1)*Wv + x0]     : 0.f;
            float v11 = ((unsigned)(y0+1) < Hv && (unsigned)(x0+1) < Wv) ? mb[(y0+1)*Wv + x0 + 1] : 0.f;
            umsum += (v00*(1.f-ly) + v10*ly)*(1.f-lx) + (v01*(1.f-ly) + v11*ly)*lx;
        }
    }
    out[(size_t)Bv*COUTv*HWv + (size_t)b*HWv + hw] = fminf(fmaxf(64.f * umsum, 0.f), 1.f);
}

// ---------------- kernel: coalesced bilinear gather -> im2col S ----------------
__global__ void __launch_bounds__(128)
k_gather() {
    __shared__ float sm[4][32][33];
    int warp = threadIdx.x >> 5;
    int l    = threadIdx.x & 31;           // lane = channel within group
    int pix0 = blockIdx.x * 32;
    int b    = pix0 / HWv;
    int hw0  = pix0 % HWv;

    for (int kk = warp; kk < 18; kk += 4) {
        int g = kk / 9;
        int idx = kk * HWv + (size_t)b * (18 * HWv) + hw0;
        float py = g_py[idx + l];
        float px = g_px[idx + l];
        float dm = g_dm[idx + l];
        const float* xb = g_nhwc + ((size_t)b * HWv) * 64 + g * 32 + l;

        #pragma unroll 4
        for (int p = 0; p < 32; p++) {
            float pyp = __shfl_sync(0xffffffffu, py, p);
            float pxp = __shfl_sync(0xffffffffu, px, p);
            float dmp = __shfl_sync(0xffffffffu, dm, p);
            float y0f = floorf(pyp), x0f = floorf(pxp);
            int y0 = (int)y0f, x0 = (int)x0f;
            float ly = pyp - y0f, lx = pxp - x0f;
            bool vy0 = (unsigned)y0       < Hv;
            bool vy1 = (unsigned)(y0 + 1) < Hv;
            bool vx0 = (unsigned)x0       < Wv;
            bool vx1 = (unsigned)(x0 + 1) < Wv;
            float v00 = 0.f, v01 = 0.f, v10 = 0.f, v11 = 0.f;
            if (vy0 && vx0) v00 = xb[(y0*Wv + x0) * 64];
            if (vy0 && vx1) v01 = xb[(y0*Wv + x0 + 1) * 64];
            if (vy1 && vx0) v10 = xb[((y0+1)*Wv + x0) * 64];
            if (vy1 && vx1) v11 = xb[((y0+1)*Wv + x0 + 1) * 64];
            float val = ((v00*(1.f-ly) + v10*ly)*(1.f-lx)
                       + (v01*(1.f-ly) + v11*ly)*lx) * dmp;
            sm[warp][l][p] = val;
        }
        __syncwarp();
        int slabbase = (b * 18 + kk) * 8;
        #pragma unroll
        for (int q = 0; q < 8; q++) {
            float4 v;
            v.x = sm[warp][4*q + 0][l];
            v.y = sm[warp][4*q + 1][l];
            v.z = sm[warp][4*q + 2][l];
            v.w = sm[warp][4*q + 3][l];
            g_S[(size_t)(slabbase + q) * HWv + hw0 + l] = v;
        }
        __syncwarp();
    }
}

// ---------------- kernel: register-blocked GEMM out = W(64x576) * S(576xHW) ----------------
// block 256 thr: tile 64o x 256px, thread micro-tile 8o x 8px (32 f32x2 accs).
// Per c-step per warp: 2 lane-varying LDS.128 + 2 broadcast LDS.128 for 32 FFMA2.
__global__ void __launch_bounds__(256, 2)
k_gemm(const float* __restrict__ bias, float* __restrict__ out) {
    __shared__ float Wsm[32 * 64];    // [c][o]
    __shared__ float Ssm[32 * 256];   // [c][p]
    int t   = threadIdx.x;
    int b   = blockIdx.x / (HWv / 256);
    int hw0 = (blockIdx.x % (HWv / 256)) * 256;
    int po  = (t >> 5) << 3;     // output-channel base: warp-uniform (0..56)
    int pp  = (t & 31) << 3;     // pixel base (0..248)

    unsigned long long acc[32];
    #pragma unroll
    for (int j = 0; j < 32; j++) acc[j] = 0ull;

    #pragma unroll 1
    for (int kk = 0; kk < 18; kk++) {
        __syncthreads();
        // stage weights: 2048 floats
        const float4* wsrc = (const float4*)(g_wt + kk * 2048);
        ((float4*)Wsm)[t]       = wsrc[t];
        ((float4*)Wsm)[t + 256] = wsrc[t + 256];
        // stage S slice: 32c x 256p
        int base = (b * 18 + kk) * 8;
        #pragma unroll
        for (int i = 0; i < 8; i++) {
            int f = t + i * 256;           // 0..2047
            int q = f >> 8, p = f & 255;
            float4 v = g_S[(size_t)(base + q) * HWv + hw0 + p];
            Ssm[(4*q + 0) * 256 + p] = v.x;
            Ssm[(4*q + 1) * 256 + p] = v.y;
            Ssm[(4*q + 2) * 256 + p] = v.z;
            Ssm[(4*q + 3) * 256 + p] = v.w;
        }
        __syncthreads();
        #pragma unroll 4
        for (int c = 0; c < 32; c++) {
            ulonglong2 s01 = *(const ulonglong2*)(Ssm + c * 256 + pp);
            ulonglong2 s23 = *(const ulonglong2*)(Ssm + c * 256 + pp + 4);
            float4 w0 = *(const float4*)(Wsm + c * 64 + po);
            float4 w1 = *(const float4*)(Wsm + c * 64 + po + 4);
            float wa[8] = {w0.x, w0.y, w0.z, w0.w, w1.x, w1.y, w1.z, w1.w};
            #pragma unroll
            for (int e = 0; e < 8; e++) {
                unsigned long long w2 = pack2(wa[e], wa[e]);
                ffma2(acc[e*4 + 0], w2, s01.x);
                ffma2(acc[e*4 + 1], w2, s01.y);
                ffma2(acc[e*4 + 2], w2, s23.x);
                ffma2(acc[e*4 + 3], w2, s23.y);
            }
        }
    }

    // epilogue: (acc + bias) * update_mask
    const float* umP = out + (size_t)Bv*COUTv*HWv + (size_t)b*HWv + hw0 + pp;
    float4 um0 = *(const float4*)(umP);
    float4 um1 = *(const float4*)(umP + 4);
    #pragma unroll
    for (int e = 0; e < 8; e++) {
        float bv = bias[po + e];
        float2 r0 = unpack2(acc[e*4 + 0]);
        float2 r1 = unpack2(acc[e*4 + 1]);
        float2 r2 = unpack2(acc[e*4 + 2]);
        float2 r3 = unpack2(acc[e*4 + 3]);
        float* op = out + ((size_t)b*COUTv + po + e)*HWv + hw0 + pp;
        float4 o0 = {(r0.x + bv)*um0.x, (r0.y + bv)*um0.y,
                     (r1.x + bv)*um0.z, (r1.y + bv)*um0.w};
        float4 o1 = {(r2.x + bv)*um1.x, (r2.y + bv)*um1.y,
                     (r3.x + bv)*um1.z, (r3.y + bv)*um1.w};
        *(float4*)op       = o0;
        *(float4*)(op + 4) = o1;
    }
}

// ---------------- launcher ----------------
extern "C" void kernel_launch(void* const* d_in, const int* in_sizes, int n_in,
                              void* d_out, int out_size) {
    const float* input  = (const float*)d_in[0];
    const float* mask   = (const float*)d_in[1];
    const float* weight = (const float*)d_in[2];
    const float* bias   = (const float*)d_in[3];
    const float* sem_w  = (const float*)d_in[4];
    const float* sem_b  = (const float*)d_in[5];
    const float* reg_w  = (const float*)d_in[6];
    const float* reg_b  = (const float*)d_in[7];
    const float* m1_w   = (const float*)d_in[8];
    const float* m1_b   = (const float*)d_in[9];
    const float* m2_w   = (const float*)d_in[10];
    const float* m2_b   = (const float*)d_in[11];
    float* out = (float*)d_out;

    cudaFuncSetAttribute(k_offsets, cudaFuncAttributeMaxDynamicSharedMemorySize, KKv*64*28*4);

    k_transpose<<<dim3(Wv/32, Hv, Bv), 256>>>(input);
    k_prep<<<(Gv*KKv*CGv*COUTv + 255)/256, 256>>>(weight, sem_w, m2_w);
    k_offsets<<<(Bv*HWv)/128, 128, KKv*64*28*4>>>(mask, sem_b, reg_w, reg_b,
                                                  m1_w, m1_b, m2_b, out);
    k_gather<<<(Bv*HWv)/32, 128>>>();
    k_gemm<<<(Bv*HWv)/256, 256>>>(bias, out);
}

// round 4
// speedup vs baseline: 1.2606x; 1.0117x over previous
#include <cuda_runtime.h>

#define Bv 2
#define CINv 64
#define COUTv 64
#define Hv 192
#define Wv 192
#define Gv 2
#define KKv 9
#define CGv 32
#define HWv (Hv*Wv)

// ---------------- scratch (__device__ globals; no runtime alloc) ----------------
__device__ float g_nhwc[Bv*Hv*Wv*CINv];        // input transposed to NHWC
__device__ float g_py  [Bv*Gv*KKv*HWv];        // absolute sample y
__device__ float g_px  [Bv*Gv*KKv*HWv];        // absolute sample x
__device__ float g_dm  [Bv*Gv*KKv*HWv];        // modulation mask (post-sigmoid)
__device__ float g_wt  [Gv*KKv*CGv*COUTv];     // main weight transposed [g][k][c][o]
__device__ float g_wk  [KKv*64*28];            // sem+m2 weights transposed [k][c][oc(28)]
__device__ float4 g_S  [Bv*Gv*KKv*8*HWv];      // sampled+modulated im2col

// ---------------- f32x2 packed helpers ----------------
__device__ __forceinline__ unsigned long long pack2(float lo, float hi) {
    unsigned long long r;
    asm("mov.b64 %0, {%1, %2};" : "=l"(r) : "f"(lo), "f"(hi));
    return r;
}
__device__ __forceinline__ void ffma2(unsigned long long &d,
                                      unsigned long long a,
                                      unsigned long long b) {
    asm("fma.rn.f32x2 %0, %1, %2, %0;" : "+l"(d) : "l"(a), "l"(b));
}
__device__ __forceinline__ float2 unpack2(unsigned long long v) {
    float2 r;
    asm("mov.b64 {%0, %1}, %2;" : "=f"(r.x), "=f"(r.y) : "l"(v));
    return r;
}

// ---------------- kernel: NCHW -> NHWC transpose (smem tiled) ----------------
__global__ void k_transpose(const float* __restrict__ in) {
    __shared__ float tile[64][33];
    int b  = blockIdx.z;
    int h  = blockIdx.y;
    int w0 = blockIdx.x * 32;
    int tw = threadIdx.x & 31;
    int tc = threadIdx.x >> 5;
    #pragma unroll
    for (int c = tc; c < 64; c += 8)
        tile[c][tw] = in[(((size_t)b*CINv + c)*Hv + h)*Wv + w0 + tw];
    __syncthreads();
    int oc = threadIdx.x & 63;
    #pragma unroll
    for (int j = threadIdx.x >> 6; j < 32; j += 4)
        g_nhwc[(((size_t)b*Hv + h)*Wv + w0 + j)*CINv + oc] = tile[oc][j];
}

// ---------------- kernel: transpose weights into gather-friendly layouts ----------------
__global__ void k_prep(const float* __restrict__ weight,
                       const float* __restrict__ sem_w,
                       const float* __restrict__ m2_w) {
    int i = blockIdx.x * 256 + threadIdx.x;
    if (i < Gv*KKv*CGv*COUTv) {
        int o = i & 63;
        int c = (i >> 6) & 31;
        int k = (i >> 11) % KKv;
        int g = i / (2048 * KKv);
        g_wt[i] = weight[((size_t)o*CINv + g*CGv + c)*KKv + k];
    }
    if (i < KKv*64*28) {
        int oc = i % 28;
        int c  = (i / 28) % 64;
        int k  = i / (28 * 64);
        float v = 0.f;
        if (oc < 18)      v = sem_w[((size_t)oc*64 + c)*KKv + k];
        else if (oc < 27) v = m2_w[((size_t)(oc-18)*64 + c)*KKv + k];
        g_wk[i] = v;
    }
}

// ---------------- kernel: offsets + modulation masks + update_mask ----------------
__global__ void __launch_bounds__(128)
k_offsets(const float* __restrict__ mask,
          const float* __restrict__ sem_b,
          const float* __restrict__ reg_w, const float* __restrict__ reg_b,
          const float* __restrict__ m1_w,  const float* __restrict__ m1_b,
          const float* __restrict__ m2_b,
          float* __restrict__ out) {
    extern __shared__ float wsm[];   // [k][c][28] = 16128 floats
    for (int i = threadIdx.x * 4; i < KKv*64*28; i += 128 * 4)
        *(float4*)(wsm + i) = *(const float4*)(g_wk + i);
    __syncthreads();

    int pix = blockIdx.x * 128 + threadIdx.x;
    int b  = pix / HWv;
    int hw = pix % HWv;
    int h  = hw / Wv;
    int w  = hw % Wv;

    unsigned long long acc[14];
    #pragma unroll
    for (int j = 0; j < 14; j++) {
        int a = 2*j, c2 = 2*j + 1;
        float lo = (a  < 18) ? sem_b[a]  : ((a  < 27) ? m2_b[a  - 18] : 0.f);
        float hi = (c2 < 18) ? sem_b[c2] : ((c2 < 27) ? m2_b[c2 - 18] : 0.f);
        acc[j] = pack2(lo, hi);
    }

    #pragma unroll 1
    for (int k = 0; k < 9; k++) {
        int yy = h + k / 3 - 1, xx = w + k % 3 - 1;
        if ((unsigned)yy < Hv && (unsigned)xx < Wv) {
            const float4* p = (const float4*)(g_nhwc + (((size_t)b*Hv + yy)*Wv + xx)*64);
            const float* wrow = wsm + k * 64 * 28;
            #pragma unroll 2
            for (int c4 = 0; c4 < 16; c4++) {
                float4 v = p[c4];
                float sarr[4] = {v.x, v.y, v.z, v.w};
                #pragma unroll
                for (int e = 0; e < 4; e++) {
                    unsigned long long s2 = pack2(sarr[e], sarr[e]);
                    const ulonglong2* wp = (const ulonglong2*)(wrow + (c4*4 + e) * 28);
                    #pragma unroll
                    for (int j2 = 0; j2 < 7; j2++) {
                        ulonglong2 q = wp[j2];
                        ffma2(acc[2*j2],     s2, q.x);
                        ffma2(acc[2*j2 + 1], s2, q.y);
                    }
                }
            }
        }
    }
    float res[28];
    #pragma unroll
    for (int j = 0; j < 14; j++) { float2 t = unpack2(acc[j]); res[2*j] = t.x; res[2*j+1] = t.y; }

    float mv[9];
    #pragma unroll
    for (int k = 0; k < 9; k++) {
        int yy = h + k / 3 - 1, xx = w + k % 3 - 1;
        mv[k] = ((unsigned)yy < Hv && (unsigned)xx < Wv) ? mask[(size_t)b*HWv + yy*Wv + xx] : 0.f;
    }
    float ro[18];
    #pragma unroll
    for (int i = 0; i < 18; i++) {
        float s = reg_b[i];
        #pragma unroll
        for (int k = 0; k < 9; k++) s += mv[k] * __ldg(&reg_w[i*9 + k]);
        ro[i] = s;
    }
    float d1[9];
    #pragma unroll
    for (int j = 0; j < 9; j++) {
        float s = m1_b[j];
        #pragma unroll
        for (int k = 0; k < 9; k++) s += mv[k] * __ldg(&m1_w[j*9 + k]);
        d1[j] = 1.f / (1.f + __expf(-s));
    }

    const float* mb = mask + (size_t)b * HWv;
    float umsum = 0.f;
    #pragma unroll
    for (int g = 0; g < 2; g++) {
        #pragma unroll
        for (int k = 0; k < 9; k++) {
            float dy = g ? res[2*k]     : ro[2*k];
            float dx = g ? res[2*k + 1] : ro[2*k + 1];
            float py = dy + (float)h + (float)(k / 3 - 1);
            float px = dx + (float)w + (float)(k % 3 - 1);
            int idx = (((b*2 + g)*9) + k) * HWv + hw;
            g_py[idx] = py;
            g_px[idx] = px;
            g_dm[idx] = g ? (1.f / (1.f + __expf(-res[18 + k]))) : d1[k];

            float y0f = floorf(py), x0f = floorf(px);
            int y0 = (int)y0f, x0 = (int)x0f;
            float ly = py - y0f, lx = px - x0f;
            float v00 = ((unsigned)y0     < Hv && (unsigned)x0     < Wv) ? mb[y0*Wv + x0]         : 0.f;
            float v01 = ((unsigned)y0     < Hv && (unsigned)(x0+1) < Wv) ? mb[y0*Wv + x0 + 1]     : 0.f;
            float v10 = ((unsigned)(y0+1) < Hv && (unsigned)x0     < Wv) ? mb[(y0+1)*Wv + x0]     : 0.f;
            float v11 = ((unsigned)(y0+1) < Hv && (unsigned)(x0+1) < Wv) ? mb[(y0+1)*Wv + x0 + 1] : 0.f;
            umsum += (v00*(1.f-ly) + v10*ly)*(1.f-lx) + (v01*(1.f-ly) + v11*ly)*lx;
        }
    }
    out[(size_t)Bv*COUTv*HWv + (size_t)b*HWv + hw] = fminf(fmaxf(64.f * umsum, 0.f), 1.f);
}

// ---------------- kernel: coalesced bilinear gather -> im2col S ----------------
// Phase 1: 128 threads precompute per-(kk,pixel) corner offsets (clamped) and
// bilinear weights premultiplied by the modulation mask -> SMEM. No SHFLs.
// Phase 2: lane = channel; per pixel 2 broadcast LDS.128 + 4 coalesced LDG +
// 4 FFMA + 1 STS. Unrolled for MLP.
__global__ void __launch_bounds__(128)
k_gather() {
    __shared__ int4   po[18][32];
    __shared__ float4 pw[18][32];
    __shared__ float  sm[4][32][33];
    int tid  = threadIdx.x;
    int pix0 = blockIdx.x * 32;
    int b    = pix0 / HWv;
    int hw0  = pix0 % HWv;

    #pragma unroll
    for (int it = 0; it < 5; it++) {
        int idx = tid + it * 128;
        if (idx < 576) {
            int kk = idx >> 5;
            int p  = idx & 31;
            int gi = (b * 18 + kk) * HWv + hw0 + p;
            float py = g_py[gi], px = g_px[gi], dm = g_dm[gi];
            float y0f = floorf(py), x0f = floorf(px);
            int y0 = (int)y0f, x0 = (int)x0f;
            float ly = py - y0f, lx = px - x0f;
            bool vy0 = (unsigned)y0       < Hv;
            bool vy1 = (unsigned)(y0 + 1) < Hv;
            bool vx0 = (unsigned)x0       < Wv;
            bool vx1 = (unsigned)(x0 + 1) < Wv;
            float w00 = (vy0 && vx0) ? (1.f-ly)*(1.f-lx)*dm : 0.f;
            float w01 = (vy0 && vx1) ? (1.f-ly)*lx*dm       : 0.f;
            float w10 = (vy1 && vx0) ? ly*(1.f-lx)*dm       : 0.f;
            float w11 = (vy1 && vx1) ? ly*lx*dm             : 0.f;
            int yc0 = min(max(y0, 0), Hv-1),   yc1 = min(max(y0+1, 0), Hv-1);
            int xc0 = min(max(x0, 0), Wv-1),   xc1 = min(max(x0+1, 0), Wv-1);
            po[kk][p] = make_int4((yc0*Wv + xc0)*64, (yc0*Wv + xc1)*64,
                                  (yc1*Wv + xc0)*64, (yc1*Wv + xc1)*64);
            pw[kk][p] = make_float4(w00, w01, w10, w11);
        }
    }
    __syncthreads();

    int warp = tid >> 5;
    int l    = tid & 31;

    #pragma unroll 1
    for (int kk = warp; kk < 18; kk += 4) {
        const float* xb = g_nhwc + ((size_t)b * HWv) * 64 + (kk / 9) * 32 + l;
        #pragma unroll 8
        for (int p = 0; p < 32; p++) {
            int4   o  = po[kk][p];
            float4 wv = pw[kk][p];
            float v = xb[o.x]*wv.x + xb[o.y]*wv.y + xb[o.z]*wv.z + xb[o.w]*wv.w;
            sm[warp][l][p] = v;
        }
        __syncwarp();
        int slabbase = (b * 18 + kk) * 8;
        #pragma unroll
        for (int q = 0; q < 8; q++) {
            float4 v;
            v.x = sm[warp][4*q + 0][l];
            v.y = sm[warp][4*q + 1][l];
            v.z = sm[warp][4*q + 2][l];
            v.w = sm[warp][4*q + 3][l];
            g_S[(size_t)(slabbase + q) * HWv + hw0 + l] = v;
        }
        __syncwarp();
    }
}

// ---------------- kernel: register-blocked GEMM out = W(64x576) * S(576xHW) ----------------
__global__ void __launch_bounds__(256, 2)
k_gemm(const float* __restrict__ bias, float* __restrict__ out) {
    __shared__ float Wsm[32 * 64];    // [c][o]
    __shared__ float Ssm[32 * 256];   // [c][p]
    int t   = threadIdx.x;
    int b   = blockIdx.x / (HWv / 256);
    int hw0 = (blockIdx.x % (HWv / 256)) * 256;
    int po  = (t >> 5) << 3;
    int pp  = (t & 31) << 3;

    unsigned long long acc[32];
    #pragma unroll
    for (int j = 0; j < 32; j++) acc[j] = 0ull;

    #pragma unroll 1
    for (int kk = 0; kk < 18; kk++) {
        __syncthreads();
        const float4* wsrc = (const float4*)(g_wt + kk * 2048);
        ((float4*)Wsm)[t]       = wsrc[t];
        ((float4*)Wsm)[t + 256] = wsrc[t + 256];
        int base = (b * 18 + kk) * 8;
        #pragma unroll
        for (int i = 0; i < 8; i++) {
            int f = t + i * 256;
            int q = f >> 8, p = f & 255;
            float4 v = g_S[(size_t)(base + q) * HWv + hw0 + p];
            Ssm[(4*q + 0) * 256 + p] = v.x;
            Ssm[(4*q + 1) * 256 + p] = v.y;
            Ssm[(4*q + 2) * 256 + p] = v.z;
            Ssm[(4*q + 3) * 256 + p] = v.w;
        }
        __syncthreads();
        #pragma unroll 4
        for (int c = 0; c < 32; c++) {
            ulonglong2 s01 = *(const ulonglong2*)(Ssm + c * 256 + pp);
            ulonglong2 s23 = *(const ulonglong2*)(Ssm + c * 256 + pp + 4);
            float4 w0 = *(const float4*)(Wsm + c * 64 + po);
            float4 w1 = *(const float4*)(Wsm + c * 64 + po + 4);
            float wa[8] = {w0.x, w0.y, w0.z, w0.w, w1.x, w1.y, w1.z, w1.w};
            #pragma unroll
            for (int e = 0; e < 8; e++) {
                unsigned long long w2 = pack2(wa[e], wa[e]);
                ffma2(acc[e*4 + 0], w2, s01.x);
                ffma2(acc[e*4 + 1], w2, s01.y);
                ffma2(acc[e*4 + 2], w2, s23.x);
                ffma2(acc[e*4 + 3], w2, s23.y);
            }
        }
    }

    const float* umP = out + (size_t)Bv*COUTv*HWv + (size_t)b*HWv + hw0 + pp;
    float4 um0 = *(const float4*)(umP);
    float4 um1 = *(const float4*)(umP + 4);
    #pragma unroll
    for (int e = 0; e < 8; e++) {
        float bv = bias[po + e];
        float2 r0 = unpack2(acc[e*4 + 0]);
        float2 r1 = unpack2(acc[e*4 + 1]);
        float2 r2 = unpack2(acc[e*4 + 2]);
        float2 r3 = unpack2(acc[e*4 + 3]);
        float* op = out + ((size_t)b*COUTv + po + e)*HWv + hw0 + pp;
        float4 o0 = {(r0.x + bv)*um0.x, (r0.y + bv)*um0.y,
                     (r1.x + bv)*um0.z, (r1.y + bv)*um0.w};
        float4 o1 = {(r2.x + bv)*um1.x, (r2.y + bv)*um1.y,
                     (r3.x + bv)*um1.z, (r3.y + bv)*um1.w};
        *(float4*)op       = o0;
        *(float4*)(op + 4) = o1;
    }
}

// ---------------- launcher ----------------
extern "C" void kernel_launch(void* const* d_in, const int* in_sizes, int n_in,
                              void* d_out, int out_size) {
    const float* input  = (const float*)d_in[0];
    const float* mask   = (const float*)d_in[1];
    const float* weight = (const float*)d_in[2];
    const float* bias   = (const float*)d_in[3];
    const float* sem_w  = (const float*)d_in[4];
    const float* sem_b  = (const float*)d_in[5];
    const float* reg_w  = (const float*)d_in[6];
    const float* reg_b  = (const float*)d_in[7];
    const float* m1_w   = (const float*)d_in[8];
    const float* m1_b   = (const float*)d_in[9];
    const float* m2_w   = (const float*)d_in[10];
    const float* m2_b   = (const float*)d_in[11];
    float* out = (float*)d_out;

    cudaFuncSetAttribute(k_offsets, cudaFuncAttributeMaxDynamicSharedMemorySize, KKv*64*28*4);

    k_transpose<<<dim3(Wv/32, Hv, Bv), 256>>>(input);
    k_prep<<<(Gv*KKv*CGv*COUTv + 255)/256, 256>>>(weight, sem_w, m2_w);
    k_offsets<<<(Bv*HWv)/128, 128, KKv*64*28*4>>>(mask, sem_b, reg_w, reg_b,
                                                  m1_w, m1_b, m2_b, out);
    k_gather<<<(Bv*HWv)/32, 128>>>();
    k_gemm<<<(Bv*HWv)/256, 256>>>(bias, out);
}

// round 5
// speedup vs baseline: 1.6203x; 1.2854x over previous
#include <cuda_runtime.h>

#define Bv 2
#define CINv 64
#define COUTv 64
#define Hv 192
#define Wv 192
#define Gv 2
#define KKv 9
#define CGv 32
#define HWv (Hv*Wv)
#define SSTR 260   // Ssm row stride in floats (mod 4 == 0, bank-shifting)

// ---------------- scratch (__device__ globals; no runtime alloc) ----------------
__device__ float g_nhwc[Bv*Hv*Wv*CINv];        // input transposed to NHWC
__device__ float g_py  [Bv*Gv*KKv*HWv];        // absolute sample y
__device__ float g_px  [Bv*Gv*KKv*HWv];        // absolute sample x
__device__ float g_dm  [Bv*Gv*KKv*HWv];        // modulation mask (post-sigmoid)
__device__ float g_wt  [Gv*KKv*CGv*COUTv];     // main weight transposed [g][k][c][o]
__device__ float g_wk  [KKv*64*28];            // sem+m2 weights transposed [k][c][oc(28)]

// ---------------- f32x2 packed helpers ----------------
__device__ __forceinline__ unsigned long long pack2(float lo, float hi) {
    unsigned long long r;
    asm("mov.b64 %0, {%1, %2};" : "=l"(r) : "f"(lo), "f"(hi));
    return r;
}
__device__ __forceinline__ void ffma2(unsigned long long &d,
                                      unsigned long long a,
                                      unsigned long long b) {
    asm("fma.rn.f32x2 %0, %1, %2, %0;" : "+l"(d) : "l"(a), "l"(b));
}
__device__ __forceinline__ float2 unpack2(unsigned long long v) {
    float2 r;
    asm("mov.b64 {%0, %1}, %2;" : "=f"(r.x), "=f"(r.y) : "l"(v));
    return r;
}

// ---------------- kernel: NCHW -> NHWC transpose (smem tiled) ----------------
__global__ void k_transpose(const float* __restrict__ in) {
    __shared__ float tile[64][33];
    int b  = blockIdx.z;
    int h  = blockIdx.y;
    int w0 = blockIdx.x * 32;
    int tw = threadIdx.x & 31;
    int tc = threadIdx.x >> 5;
    #pragma unroll
    for (int c = tc; c < 64; c += 8)
        tile[c][tw] = in[(((size_t)b*CINv + c)*Hv + h)*Wv + w0 + tw];
    __syncthreads();
    int oc = threadIdx.x & 63;
    #pragma unroll
    for (int j = threadIdx.x >> 6; j < 32; j += 4)
        g_nhwc[(((size_t)b*Hv + h)*Wv + w0 + j)*CINv + oc] = tile[oc][j];
}

// ---------------- kernel: transpose weights into gather-friendly layouts ----------------
__global__ void k_prep(const float* __restrict__ weight,
                       const float* __restrict__ sem_w,
                       const float* __restrict__ m2_w) {
    int i = blockIdx.x * 256 + threadIdx.x;
    if (i < Gv*KKv*CGv*COUTv) {
        int o = i & 63;
        int c = (i >> 6) & 31;
        int k = (i >> 11) % KKv;
        int g = i / (2048 * KKv);
        g_wt[i] = weight[((size_t)o*CINv + g*CGv + c)*KKv + k];
    }
    if (i < KKv*64*28) {
        int oc = i % 28;
        int c  = (i / 28) % 64;
        int k  = i / (28 * 64);
        float v = 0.f;
        if (oc < 18)      v = sem_w[((size_t)oc*64 + c)*KKv + k];
        else if (oc < 27) v = m2_w[((size_t)(oc-18)*64 + c)*KKv + k];
        g_wk[i] = v;
    }
}

// ---------------- kernel: offsets + modulation masks + update_mask ----------------
__global__ void __launch_bounds__(128)
k_offsets(const float* __restrict__ mask,
          const float* __restrict__ sem_b,
          const float* __restrict__ reg_w, const float* __restrict__ reg_b,
          const float* __restrict__ m1_w,  const float* __restrict__ m1_b,
          const float* __restrict__ m2_b,
          float* __restrict__ out) {
    extern __shared__ float wsm[];   // [k][c][28] = 16128 floats
    for (int i = threadIdx.x * 4; i < KKv*64*28; i += 128 * 4)
        *(float4*)(wsm + i) = *(const float4*)(g_wk + i);
    __syncthreads();

    int pix = blockIdx.x * 128 + threadIdx.x;
    int b  = pix / HWv;
    int hw = pix % HWv;
    int h  = hw / Wv;
    int w  = hw % Wv;

    unsigned long long acc[14];
    #pragma unroll
    for (int j = 0; j < 14; j++) {
        int a = 2*j, c2 = 2*j + 1;
        float lo = (a  < 18) ? sem_b[a]  : ((a  < 27) ? m2_b[a  - 18] : 0.f);
        float hi = (c2 < 18) ? sem_b[c2] : ((c2 < 27) ? m2_b[c2 - 18] : 0.f);
        acc[j] = pack2(lo, hi);
    }

    #pragma unroll 1
    for (int k = 0; k < 9; k++) {
        int yy = h + k / 3 - 1, xx = w + k % 3 - 1;
        if ((unsigned)yy < Hv && (unsigned)xx < Wv) {
            const float4* p = (const float4*)(g_nhwc + (((size_t)b*Hv + yy)*Wv + xx)*64);
            const float* wrow = wsm + k * 64 * 28;
            #pragma unroll 2
            for (int c4 = 0; c4 < 16; c4++) {
                float4 v = p[c4];
                float sarr[4] = {v.x, v.y, v.z, v.w};
                #pragma unroll
                for (int e = 0; e < 4; e++) {
                    unsigned long long s2 = pack2(sarr[e], sarr[e]);
                    const ulonglong2* wp = (const ulonglong2*)(wrow + (c4*4 + e) * 28);
                    #pragma unroll
                    for (int j2 = 0; j2 < 7; j2++) {
                        ulonglong2 q = wp[j2];
                        ffma2(acc[2*j2],     s2, q.x);
                        ffma2(acc[2*j2 + 1], s2, q.y);
                    }
                }
            }
        }
    }
    float res[28];
    #pragma unroll
    for (int j = 0; j < 14; j++) { float2 t = unpack2(acc[j]); res[2*j] = t.x; res[2*j+1] = t.y; }

    float mv[9];
    #pragma unroll
    for (int k = 0; k < 9; k++) {
        int yy = h + k / 3 - 1, xx = w + k % 3 - 1;
        mv[k] = ((unsigned)yy < Hv && (unsigned)xx < Wv) ? mask[(size_t)b*HWv + yy*Wv + xx] : 0.f;
    }
    float ro[18];
    #pragma unroll
    for (int i = 0; i < 18; i++) {
        float s = reg_b[i];
        #pragma unroll
        for (int k = 0; k < 9; k++) s += mv[k] * __ldg(&reg_w[i*9 + k]);
        ro[i] = s;
    }
    float d1[9];
    #pragma unroll
    for (int j = 0; j < 9; j++) {
        float s = m1_b[j];
        #pragma unroll
        for (int k = 0; k < 9; k++) s += mv[k] * __ldg(&m1_w[j*9 + k]);
        d1[j] = 1.f / (1.f + __expf(-s));
    }

    const float* mb = mask + (size_t)b * HWv;
    float umsum = 0.f;
    #pragma unroll
    for (int g = 0; g < 2; g++) {
        #pragma unroll
        for (int k = 0; k < 9; k++) {
            float dy = g ? res[2*k]     : ro[2*k];
            float dx = g ? res[2*k + 1] : ro[2*k + 1];
            float py = dy + (float)h + (float)(k / 3 - 1);
            float px = dx + (float)w + (float)(k % 3 - 1);
            int idx = (((b*2 + g)*9) + k) * HWv + hw;
            g_py[idx] = py;
            g_px[idx] = px;
            g_dm[idx] = g ? (1.f / (1.f + __expf(-res[18 + k]))) : d1[k];

            float y0f = floorf(py), x0f = floorf(px);
            int y0 = (int)y0f, x0 = (int)x0f;
            float ly = py - y0f, lx = px - x0f;
            float v00 = ((unsigned)y0     < Hv && (unsigned)x0     < Wv) ? mb[y0*Wv + x0]         : 0.f;
            float v01 = ((unsigned)y0     < Hv && (unsigned)(x0+1) < Wv) ? mb[y0*Wv + x0 + 1]     : 0.f;
            float v10 = ((unsigned)(y0+1) < Hv && (unsigned)x0     < Wv) ? mb[(y0+1)*Wv + x0]     : 0.f;
            float v11 = ((unsigned)(y0+1) < Hv && (unsigned)(x0+1) < Wv) ? mb[(y0+1)*Wv + x0 + 1] : 0.f;
            umsum += (v00*(1.f-ly) + v10*ly)*(1.f-lx) + (v01*(1.f-ly) + v11*ly)*lx;
        }
    }
    out[(size_t)Bv*COUTv*HWv + (size_t)b*HWv + hw] = fminf(fmaxf(64.f * umsum, 0.f), 1.f);
}

// ---------------- fused gather + GEMM ----------------
// block = 256 thr (8 warps), tile = 64 outch x 256 pixels.
// Per kk (18 slices of 32 channels):
//   1. thread t computes po/pw (clamped corner offsets, premult bilinear weights)
//      for pixel hw0+t; also stages W slice.
//   2. warp w gathers channel lane for pixels [32w,32w+32): 4 coalesced LDG per px,
//      packs 4 px into float4, conflict-free STS.128 into Ssm[c][p] (stride 260).
//   3. fma loop: thread tile 8o x (4px @4ps + 4px @128+4ps) -> LDS.128 spans all
//      32 banks (4 wf, no conflicts).
__global__ void __launch_bounds__(256, 2)
k_fused(const float* __restrict__ bias, float* __restrict__ out) {
    extern __shared__ float dsm[];
    float*  Wsm = dsm;                    // 2048 floats [c][o]
    float*  Ssm = dsm + 2048;             // 32*SSTR floats [c][p]
    int4*   po  = (int4*)(dsm + 2048 + 32*SSTR);
    float4* pw  = (float4*)(po + 256);

    int t   = threadIdx.x;
    int w   = t >> 5, l = t & 31;
    int b   = blockIdx.x / (HWv / 256);
    int hw0 = (blockIdx.x % (HWv / 256)) * 256;
    int ob  = (t >> 5) << 3;   // out-channel base
    int ps  = t & 31;          // pixel-chunk selector

    unsigned long long acc[32];
    #pragma unroll
    for (int j = 0; j < 32; j++) acc[j] = 0ull;

    #pragma unroll 1
    for (int kk = 0; kk < 18; kk++) {
        __syncthreads();
        // stage weights for this kk
        const float4* wsrc = (const float4*)(g_wt + kk * 2048);
        ((float4*)Wsm)[t]       = wsrc[t];
        ((float4*)Wsm)[t + 256] = wsrc[t + 256];
        // per-pixel sampling params
        {
            int gi = (b * 18 + kk) * HWv + hw0 + t;
            float py = g_py[gi], px = g_px[gi], dm = g_dm[gi];
            float y0f = floorf(py), x0f = floorf(px);
            int y0 = (int)y0f, x0 = (int)x0f;
            float ly = py - y0f, lx = px - x0f;
            bool vy0 = (unsigned)y0       < Hv;
            bool vy1 = (unsigned)(y0 + 1) < Hv;
            bool vx0 = (unsigned)x0       < Wv;
            bool vx1 = (unsigned)(x0 + 1) < Wv;
            float w00 = (vy0 && vx0) ? (1.f-ly)*(1.f-lx)*dm : 0.f;
            float w01 = (vy0 && vx1) ? (1.f-ly)*lx*dm       : 0.f;
            float w10 = (vy1 && vx0) ? ly*(1.f-lx)*dm       : 0.f;
            float w11 = (vy1 && vx1) ? ly*lx*dm             : 0.f;
            int yc0 = min(max(y0, 0), Hv-1),   yc1 = min(max(y0+1, 0), Hv-1);
            int xc0 = min(max(x0, 0), Wv-1),   xc1 = min(max(x0+1, 0), Wv-1);
            po[t] = make_int4((yc0*Wv + xc0)*64, (yc0*Wv + xc1)*64,
                              (yc1*Wv + xc0)*64, (yc1*Wv + xc1)*64);
            pw[t] = make_float4(w00, w01, w10, w11);
        }
        __syncthreads();

        // gather: lane = channel, warp w covers pixels [32w, 32w+32)
        {
            const float* xb = g_nhwc + ((size_t)b * HWv) * 64 + (kk / 9) * 32 + l;
            float* srow = Ssm + l * SSTR + 32 * w;
            #pragma unroll
            for (int j = 0; j < 8; j++) {
                float v[4];
                #pragma unroll
                for (int e = 0; e < 4; e++) {
                    int p = 32*w + 4*j + e;
                    int4   o  = po[p];
                    float4 wv = pw[p];
                    v[e] = xb[o.x]*wv.x + xb[o.y]*wv.y + xb[o.z]*wv.z + xb[o.w]*wv.w;
                }
                *(float4*)(srow + 4*j) = make_float4(v[0], v[1], v[2], v[3]);
            }
        }
        __syncthreads();

        // fma: 8 outch x 8 px (two 4-px chunks at 4ps and 128+4ps)
        #pragma unroll 4
        for (int c = 0; c < 32; c++) {
            ulonglong2 s01 = *(const ulonglong2*)(Ssm + c * SSTR + 4*ps);
            ulonglong2 s23 = *(const ulonglong2*)(Ssm + c * SSTR + 128 + 4*ps);
            float4 w0 = *(const float4*)(Wsm + c * 64 + ob);
            float4 w1 = *(const float4*)(Wsm + c * 64 + ob + 4);
            float wa[8] = {w0.x, w0.y, w0.z, w0.w, w1.x, w1.y, w1.z, w1.w};
            #pragma unroll
            for (int e = 0; e < 8; e++) {
                unsigned long long w2 = pack2(wa[e], wa[e]);
                ffma2(acc[e*4 + 0], w2, s01.x);
                ffma2(acc[e*4 + 1], w2, s01.y);
                ffma2(acc[e*4 + 2], w2, s23.x);
                ffma2(acc[e*4 + 3], w2, s23.y);
            }
        }
    }

    // epilogue: (acc + bias) * update_mask
    const float* umB = out + (size_t)Bv*COUTv*HWv + (size_t)b*HWv + hw0;
    float4 um0 = *(const float4*)(umB + 4*ps);
    float4 um1 = *(const float4*)(umB + 128 + 4*ps);
    #pragma unroll
    for (int e = 0; e < 8; e++) {
        float bv = bias[ob + e];
        float2 r0 = unpack2(acc[e*4 + 0]);
        float2 r1 = unpack2(acc[e*4 + 1]);
        float2 r2 = unpack2(acc[e*4 + 2]);
        float2 r3 = unpack2(acc[e*4 + 3]);
        float* op = out + ((size_t)b*COUTv + ob + e)*HWv + hw0;
        float4 o0 = {(r0.x + bv)*um0.x, (r0.y + bv)*um0.y,
                     (r1.x + bv)*um0.z, (r1.y + bv)*um0.w};
        float4 o1 = {(r2.x + bv)*um1.x, (r2.y + bv)*um1.y,
                     (r3.x + bv)*um1.z, (r3.y + bv)*um1.w};
        *(float4*)(op + 4*ps)       = o0;
        *(float4*)(op + 128 + 4*ps) = o1;
    }
}

// ---------------- launcher ----------------
extern "C" void kernel_launch(void* const* d_in, const int* in_sizes, int n_in,
                              void* d_out, int out_size) {
    const float* input  = (const float*)d_in[0];
    const float* mask   = (const float*)d_in[1];
    const float* weight = (const float*)d_in[2];
    const float* bias   = (const float*)d_in[3];
    const float* sem_w  = (const float*)d_in[4];
    const float* sem_b  = (const float*)d_in[5];
    const float* reg_w  = (const float*)d_in[6];
    const float* reg_b  = (const float*)d_in[7];
    const float* m1_w   = (const float*)d_in[8];
    const float* m1_b   = (const float*)d_in[9];
    const float* m2_w   = (const float*)d_in[10];
    const float* m2_b   = (const float*)d_in[11];
    float* out = (float*)d_out;

    const int fusedSmem = (2048 + 32*SSTR) * 4 + 256*16 + 256*16;  // ~49.7KB

    cudaFuncSetAttribute(k_offsets, cudaFuncAttributeMaxDynamicSharedMemorySize, KKv*64*28*4);
    cudaFuncSetAttribute(k_fused,   cudaFuncAttributeMaxDynamicSharedMemorySize, fusedSmem);

    k_transpose<<<dim3(Wv/32, Hv, Bv), 256>>>(input);
    k_prep<<<(Gv*KKv*CGv*COUTv + 255)/256, 256>>>(weight, sem_w, m2_w);
    k_offsets<<<(Bv*HWv)/128, 128, KKv*64*28*4>>>(mask, sem_b, reg_w, reg_b,
                                                  m1_w, m1_b, m2_b, out);
    k_fused<<<(Bv*HWv)/256, 256, fusedSmem>>>(bias, out);
}

// round 6
// speedup vs baseline: 1.6812x; 1.0375x over previous
#include <cuda_runtime.h>

#define Bv 2
#define CINv 64
#define COUTv 64
#define Hv 192
#define Wv 192
#define Gv 2
#define KKv 9
#define CGv 32
#define HWv (Hv*Wv)
#define SSTR 260   // Ssm row stride in floats (bank-shifting, mod 4 == 0)

// ---------------- scratch (__device__ globals; no runtime alloc) ----------------
__device__ float g_nhwc[Bv*Hv*Wv*CINv];        // input transposed to NHWC (for k_fused gathers)
__device__ float g_py  [Bv*Gv*KKv*HWv];        // absolute sample y
__device__ float g_px  [Bv*Gv*KKv*HWv];        // absolute sample x
__device__ float g_dm  [Bv*Gv*KKv*HWv];        // modulation mask (post-sigmoid)
__device__ float g_wt  [Gv*KKv*CGv*COUTv];     // main weight transposed [g][k][c][o]
__device__ float g_wk  [KKv*64*28];            // sem+m2 weights transposed [k][c][oc(28)]

// ---------------- f32x2 packed helpers ----------------
__device__ __forceinline__ unsigned long long pack2(float lo, float hi) {
    unsigned long long r;
    asm("mov.b64 %0, {%1, %2};" : "=l"(r) : "f"(lo), "f"(hi));
    return r;
}
__device__ __forceinline__ void ffma2(unsigned long long &d,
                                      unsigned long long a,
                                      unsigned long long b) {
    asm("fma.rn.f32x2 %0, %1, %2, %0;" : "+l"(d) : "l"(a), "l"(b));
}
__device__ __forceinline__ float2 unpack2(unsigned long long v) {
    float2 r;
    asm("mov.b64 {%0, %1}, %2;" : "=f"(r.x), "=f"(r.y) : "l"(v));
    return r;
}

// ---------------- kernel: NCHW -> NHWC transpose (smem tiled) ----------------
__global__ void k_transpose(const float* __restrict__ in) {
    __shared__ float tile[64][33];
    int b  = blockIdx.z;
    int h  = blockIdx.y;
    int w0 = blockIdx.x * 32;
    int tw = threadIdx.x & 31;
    int tc = threadIdx.x >> 5;
    #pragma unroll
    for (int c = tc; c < 64; c += 8)
        tile[c][tw] = in[(((size_t)b*CINv + c)*Hv + h)*Wv + w0 + tw];
    __syncthreads();
    int oc = threadIdx.x & 63;
    #pragma unroll
    for (int j = threadIdx.x >> 6; j < 32; j += 4)
        g_nhwc[(((size_t)b*Hv + h)*Wv + w0 + j)*CINv + oc] = tile[oc][j];
}

// ---------------- kernel: transpose weights ----------------
__global__ void k_prep(const float* __restrict__ weight,
                       const float* __restrict__ sem_w,
                       const float* __restrict__ m2_w) {
    int i = blockIdx.x * 256 + threadIdx.x;
    if (i < Gv*KKv*CGv*COUTv) {
        int o = i & 63;
        int c = (i >> 6) & 31;
        int k = (i >> 11) % KKv;
        int g = i / (2048 * KKv);
        g_wt[i] = weight[((size_t)o*CINv + g*CGv + c)*KKv + k];
    }
    if (i < KKv*64*28) {
        int oc = i % 28;
        int c  = (i / 28) % 64;
        int k  = i / (28 * 64);
        float v = 0.f;
        if (oc < 18)      v = sem_w[((size_t)oc*64 + c)*KKv + k];
        else if (oc < 27) v = m2_w[((size_t)(oc-18)*64 + c)*KKv + k];
        g_wk[i] = v;
    }
}

// ---------------- kernel: offsets + modulation masks + update_mask ----------------
// Reads NCHW input directly: lanes = adjacent pixels -> coalesced LDG.32.
__global__ void __launch_bounds__(128)
k_offsets(const float* __restrict__ input,
          const float* __restrict__ mask,
          const float* __restrict__ sem_b,
          const float* __restrict__ reg_w, const float* __restrict__ reg_b,
          const float* __restrict__ m1_w,  const float* __restrict__ m1_b,
          const float* __restrict__ m2_b,
          float* __restrict__ out) {
    extern __shared__ float wsm[];   // [k][c][28] = 16128 floats
    for (int i = threadIdx.x * 4; i < KKv*64*28; i += 128 * 4)
        *(float4*)(wsm + i) = *(const float4*)(g_wk + i);
    __syncthreads();

    int pix = blockIdx.x * 128 + threadIdx.x;
    int b  = pix / HWv;
    int hw = pix % HWv;
    int h  = hw / Wv;
    int w  = hw % Wv;

    unsigned long long acc[14];
    #pragma unroll
    for (int j = 0; j < 14; j++) {
        int a = 2*j, c2 = 2*j + 1;
        float lo = (a  < 18) ? sem_b[a]  : ((a  < 27) ? m2_b[a  - 18] : 0.f);
        float hi = (c2 < 18) ? sem_b[c2] : ((c2 < 27) ? m2_b[c2 - 18] : 0.f);
        acc[j] = pack2(lo, hi);
    }

    #pragma unroll 1
    for (int k = 0; k < 9; k++) {
        int yy = h + k / 3 - 1, xx = w + k % 3 - 1;
        if ((unsigned)yy < Hv && (unsigned)xx < Wv) {
            const float* xp = input + (size_t)b*CINv*HWv + yy*Wv + xx;  // stride HW per channel
            const float* wrow = wsm + k * 64 * 28;
            #pragma unroll 4
            for (int c = 0; c < 64; c++) {
                float x = xp[c * HWv];
                unsigned long long s2 = pack2(x, x);
                const ulonglong2* wp = (const ulonglong2*)(wrow + c * 28);
                #pragma unroll
                for (int j2 = 0; j2 < 7; j2++) {
                    ulonglong2 q = wp[j2];
                    ffma2(acc[2*j2],     s2, q.x);
                    ffma2(acc[2*j2 + 1], s2, q.y);
                }
            }
        }
    }
    float res[28];
    #pragma unroll
    for (int j = 0; j < 14; j++) { float2 t = unpack2(acc[j]); res[2*j] = t.x; res[2*j+1] = t.y; }

    float mv[9];
    #pragma unroll
    for (int k = 0; k < 9; k++) {
        int yy = h + k / 3 - 1, xx = w + k % 3 - 1;
        mv[k] = ((unsigned)yy < Hv && (unsigned)xx < Wv) ? mask[(size_t)b*HWv + yy*Wv + xx] : 0.f;
    }
    float ro[18];
    #pragma unroll
    for (int i = 0; i < 18; i++) {
        float s = reg_b[i];
        #pragma unroll
        for (int k = 0; k < 9; k++) s += mv[k] * __ldg(&reg_w[i*9 + k]);
        ro[i] = s;
    }
    float d1[9];
    #pragma unroll
    for (int j = 0; j < 9; j++) {
        float s = m1_b[j];
        #pragma unroll
        for (int k = 0; k < 9; k++) s += mv[k] * __ldg(&m1_w[j*9 + k]);
        d1[j] = 1.f / (1.f + __expf(-s));
    }

    const float* mb = mask + (size_t)b * HWv;
    float umsum = 0.f;
    #pragma unroll
    for (int g = 0; g < 2; g++) {
        #pragma unroll
        for (int k = 0; k < 9; k++) {
            float dy = g ? res[2*k]     : ro[2*k];
            float dx = g ? res[2*k + 1] : ro[2*k + 1];
            float py = dy + (float)h + (float)(k / 3 - 1);
            float px = dx + (float)w + (float)(k % 3 - 1);
            int idx = (((b*2 + g)*9) + k) * HWv + hw;
            g_py[idx] = py;
            g_px[idx] = px;
            g_dm[idx] = g ? (1.f / (1.f + __expf(-res[18 + k]))) : d1[k];

            float y0f = floorf(py), x0f = floorf(px);
            int y0 = (int)y0f, x0 = (int)x0f;
            float ly = py - y0f, lx = px - x0f;
            float v00 = ((unsigned)y0     < Hv && (unsigned)x0     < Wv) ? mb[y0*Wv + x0]         : 0.f;
            float v01 = ((unsigned)y0     < Hv && (unsigned)(x0+1) < Wv) ? mb[y0*Wv + x0 + 1]     : 0.f;
            float v10 = ((unsigned)(y0+1) < Hv && (unsigned)x0     < Wv) ? mb[(y0+1)*Wv + x0]     : 0.f;
            float v11 = ((unsigned)(y0+1) < Hv && (unsigned)(x0+1) < Wv) ? mb[(y0+1)*Wv + x0 + 1] : 0.f;
            umsum += (v00*(1.f-ly) + v10*ly)*(1.f-lx) + (v01*(1.f-ly) + v11*ly)*lx;
        }
    }
    out[(size_t)Bv*COUTv*HWv + (size_t)b*HWv + hw] = fminf(fmaxf(64.f * umsum, 0.f), 1.f);
}

// ---------------- fused gather + GEMM ----------------
// block = 128 thr (4 warps), tile = 64 outch x 256 pixels; thread tile 16o x 8px
// (64 f32x2 accumulators). Per c-step per warp: 2 lane-varying LDS.128 (8 wf) +
// 4 broadcast LDS.128 (4 wf) for 64 FFMA2 -> fma pipe is the binding resource.
__global__ void __launch_bounds__(128, 2)
k_fused(const float* __restrict__ bias, float* __restrict__ out) {
    extern __shared__ float dsm[];
    float*  Wsm = dsm;                    // 2048 floats [c][o]
    float*  Ssm = dsm + 2048;             // 32*SSTR floats [c][p]
    int4*   po  = (int4*)(dsm + 2048 + 32*SSTR);
    float4* pw  = (float4*)(po + 256);

    int t   = threadIdx.x;
    int w   = t >> 5, l = t & 31;
    int b   = blockIdx.x / (HWv / 256);
    int hw0 = (blockIdx.x % (HWv / 256)) * 256;
    int ob  = (t >> 5) << 4;   // out-channel base (0,16,32,48)
    int ps  = t & 31;          // pixel-chunk selector

    unsigned long long acc[64];
    #pragma unroll
    for (int j = 0; j < 64; j++) acc[j] = 0ull;

    #pragma unroll 1
    for (int kk = 0; kk < 18; kk++) {
        __syncthreads();
        // stage weights for this kk (2048 floats, 4 float4 per thread)
        {
            const float4* wsrc = (const float4*)(g_wt + kk * 2048);
            #pragma unroll
            for (int i = 0; i < 4; i++)
                ((float4*)Wsm)[t + i * 128] = wsrc[t + i * 128];
        }
        // per-pixel sampling params (2 pixels per thread)
        #pragma unroll
        for (int i = 0; i < 2; i++) {
            int p  = t + i * 128;
            int gi = (b * 18 + kk) * HWv + hw0 + p;
            float py = g_py[gi], px = g_px[gi], dm = g_dm[gi];
            float y0f = floorf(py), x0f = floorf(px);
            int y0 = (int)y0f, x0 = (int)x0f;
            float ly = py - y0f, lx = px - x0f;
            bool vy0 = (unsigned)y0       < Hv;
            bool vy1 = (unsigned)(y0 + 1) < Hv;
            bool vx0 = (unsigned)x0       < Wv;
            bool vx1 = (unsigned)(x0 + 1) < Wv;
            float w00 = (vy0 && vx0) ? (1.f-ly)*(1.f-lx)*dm : 0.f;
            float w01 = (vy0 && vx1) ? (1.f-ly)*lx*dm       : 0.f;
            float w10 = (vy1 && vx0) ? ly*(1.f-lx)*dm       : 0.f;
            float w11 = (vy1 && vx1) ? ly*lx*dm             : 0.f;
            int yc0 = min(max(y0, 0), Hv-1),   yc1 = min(max(y0+1, 0), Hv-1);
            int xc0 = min(max(x0, 0), Wv-1),   xc1 = min(max(x0+1, 0), Wv-1);
            po[p] = make_int4((yc0*Wv + xc0)*64, (yc0*Wv + xc1)*64,
                              (yc1*Wv + xc0)*64, (yc1*Wv + xc1)*64);
            pw[p] = make_float4(w00, w01, w10, w11);
        }
        __syncthreads();

        // gather: lane = channel, warp w covers pixels [64w, 64w+64)
        {
            const float* xb = g_nhwc + ((size_t)b * HWv) * 64 + (kk / 9) * 32 + l;
            float* srow = Ssm + l * SSTR + 64 * w;
            #pragma unroll 4
            for (int j = 0; j < 16; j++) {
                float v[4];
                #pragma unroll
                for (int e = 0; e < 4; e++) {
                    int p = 64*w + 4*j + e;
                    int4   o  = po[p];
                    float4 wv = pw[p];
                    v[e] = xb[o.x]*wv.x + xb[o.y]*wv.y + xb[o.z]*wv.z + xb[o.w]*wv.w;
                }
                *(float4*)(srow + 4*j) = make_float4(v[0], v[1], v[2], v[3]);
            }
        }
        __syncthreads();

        // fma: 16 outch x 8 px (two 4-px chunks at 4ps and 128+4ps)
        #pragma unroll 2
        for (int c = 0; c < 32; c++) {
            ulonglong2 s01 = *(const ulonglong2*)(Ssm + c * SSTR + 4*ps);
            ulonglong2 s23 = *(const ulonglong2*)(Ssm + c * SSTR + 128 + 4*ps);
            const float4* wrow = (const float4*)(Wsm + c * 64 + ob);
            #pragma unroll
            for (int q = 0; q < 4; q++) {
                float4 wq = wrow[q];
                float wa[4] = {wq.x, wq.y, wq.z, wq.w};
                #pragma unroll
                for (int e = 0; e < 4; e++) {
                    int idx = (q*4 + e) * 4;
                    unsigned long long w2 = pack2(wa[e], wa[e]);
                    ffma2(acc[idx + 0], w2, s01.x);
                    ffma2(acc[idx + 1], w2, s01.y);
                    ffma2(acc[idx + 2], w2, s23.x);
                    ffma2(acc[idx + 3], w2, s23.y);
                }
            }
        }
    }

    // epilogue: (acc + bias) * update_mask
    const float* umB = out + (size_t)Bv*COUTv*HWv + (size_t)b*HWv + hw0;
    float4 um0 = *(const float4*)(umB + 4*ps);
    float4 um1 = *(const float4*)(umB + 128 + 4*ps);
    #pragma unroll
    for (int e = 0; e < 16; e++) {
        float bv = bias[ob + e];
        float2 r0 = unpack2(acc[e*4 + 0]);
        float2 r1 = unpack2(acc[e*4 + 1]);
        float2 r2 = unpack2(acc[e*4 + 2]);
        float2 r3 = unpack2(acc[e*4 + 3]);
        float* op = out + ((size_t)b*COUTv + ob + e)*HWv + hw0;
        float4 o0 = {(r0.x + bv)*um0.x, (r0.y + bv)*um0.y,
                     (r1.x + bv)*um0.z, (r1.y + bv)*um0.w};
        float4 o1 = {(r2.x + bv)*um1.x, (r2.y + bv)*um1.y,
                     (r3.x + bv)*um1.z, (r3.y + bv)*um1.w};
        *(float4*)(op + 4*ps)       = o0;
        *(float4*)(op + 128 + 4*ps) = o1;
    }
}

// ---------------- launcher ----------------
extern "C" void kernel_launch(void* const* d_in, const int* in_sizes, int n_in,
                              void* d_out, int out_size) {
    const float* input  = (const float*)d_in[0];
    const float* mask   = (const float*)d_in[1];
    const float* weight = (const float*)d_in[2];
    const float* bias   = (const float*)d_in[3];
    const float* sem_w  = (const float*)d_in[4];
    const float* sem_b  = (const float*)d_in[5];
    const float* reg_w  = (const float*)d_in[6];
    const float* reg_b  = (const float*)d_in[7];
    const float* m1_w   = (const float*)d_in[8];
    const float* m1_b   = (const float*)d_in[9];
    const float* m2_w   = (const float*)d_in[10];
    const float* m2_b   = (const float*)d_in[11];
    float* out = (float*)d_out;

    const int fusedSmem = (2048 + 32*SSTR) * 4 + 256*16 + 256*16;  // ~49.7KB

    cudaFuncSetAttribute(k_offsets, cudaFuncAttributeMaxDynamicSharedMemorySize, KKv*64*28*4);
    cudaFuncSetAttribute(k_fused,   cudaFuncAttributeMaxDynamicSharedMemorySize, fusedSmem);

    k_transpose<<<dim3(Wv/32, Hv, Bv), 256>>>(input);
    k_prep<<<(Gv*KKv*CGv*COUTv + 255)/256, 256>>>(weight, sem_w, m2_w);
    k_offsets<<<(Bv*HWv)/128, 128, KKv*64*28*4>>>(input, mask, sem_b, reg_w, reg_b,
                                                  m1_w, m1_b, m2_b, out);
    k_fused<<<(Bv*HWv)/256, 128, fusedSmem>>>(bias, out);
}

// round 7
// speedup vs baseline: 1.9138x; 1.1384x over previous
#include <cuda_runtime.h>

#define Bv 2
#define CINv 64
#define COUTv 64
#define Hv 192
#define Wv 192
#define Gv 2
#define KKv 9
#define CGv 32
#define HWv (Hv*Wv)
#define SSTR 260   // Ssm row stride in floats (bank-shifting, mod 4 == 0)

// ---------------- scratch (__device__ globals; no runtime alloc) ----------------
__device__ float g_nhwc[Bv*Hv*Wv*CINv];        // input transposed to NHWC (for k_fused gathers)
__device__ float g_py  [Bv*Gv*KKv*HWv];        // absolute sample y
__device__ float g_px  [Bv*Gv*KKv*HWv];        // absolute sample x
__device__ float g_dm  [Bv*Gv*KKv*HWv];        // modulation mask (post-sigmoid)
__device__ float g_wt  [Gv*KKv*CGv*COUTv];     // main weight transposed [g][k][c][o]
__device__ float g_wk  [KKv*64*28];            // sem+m2 weights transposed [k][c][oc(28)]

// ---------------- f32x2 packed helpers ----------------
__device__ __forceinline__ unsigned long long pack2(float lo, float hi) {
    unsigned long long r;
    asm("mov.b64 %0, {%1, %2};" : "=l"(r) : "f"(lo), "f"(hi));
    return r;
}
__device__ __forceinline__ void ffma2(unsigned long long &d,
                                      unsigned long long a,
                                      unsigned long long b) {
    asm("fma.rn.f32x2 %0, %1, %2, %0;" : "+l"(d) : "l"(a), "l"(b));
}
__device__ __forceinline__ float2 unpack2(unsigned long long v) {
    float2 r;
    asm("mov.b64 {%0, %1}, %2;" : "=f"(r.x), "=f"(r.y) : "l"(v));
    return r;
}

// ---------------- kernel: NCHW -> NHWC transpose (smem tiled) ----------------
__global__ void k_transpose(const float* __restrict__ in) {
    __shared__ float tile[64][33];
    int b  = blockIdx.z;
    int h  = blockIdx.y;
    int w0 = blockIdx.x * 32;
    int tw = threadIdx.x & 31;
    int tc = threadIdx.x >> 5;
    #pragma unroll
    for (int c = tc; c < 64; c += 8)
        tile[c][tw] = in[(((size_t)b*CINv + c)*Hv + h)*Wv + w0 + tw];
    __syncthreads();
    int oc = threadIdx.x & 63;
    #pragma unroll
    for (int j = threadIdx.x >> 6; j < 32; j += 4)
        g_nhwc[(((size_t)b*Hv + h)*Wv + w0 + j)*CINv + oc] = tile[oc][j];
}

// ---------------- kernel: transpose weights ----------------
__global__ void k_prep(const float* __restrict__ weight,
                       const float* __restrict__ sem_w,
                       const float* __restrict__ m2_w) {
    int i = blockIdx.x * 256 + threadIdx.x;
    if (i < Gv*KKv*CGv*COUTv) {
        int o = i & 63;
        int c = (i >> 6) & 31;
        int k = (i >> 11) % KKv;
        int g = i / (2048 * KKv);
        g_wt[i] = weight[((size_t)o*CINv + g*CGv + c)*KKv + k];
    }
    if (i < KKv*64*28) {
        int oc = i % 28;
        int c  = (i / 28) % 64;
        int k  = i / (28 * 64);
        float v = 0.f;
        if (oc < 18)      v = sem_w[((size_t)oc*64 + c)*KKv + k];
        else if (oc < 27) v = m2_w[((size_t)(oc-18)*64 + c)*KKv + k];
        g_wk[i] = v;
    }
}

// ---------------- kernel: offsets + modulation masks + update_mask ----------------
__global__ void __launch_bounds__(128)
k_offsets(const float* __restrict__ input,
          const float* __restrict__ mask,
          const float* __restrict__ sem_b,
          const float* __restrict__ reg_w, const float* __restrict__ reg_b,
          const float* __restrict__ m1_w,  const float* __restrict__ m1_b,
          const float* __restrict__ m2_b,
          float* __restrict__ out) {
    extern __shared__ float wsm[];   // [k][c][28] = 16128 floats
    for (int i = threadIdx.x * 4; i < KKv*64*28; i += 128 * 4)
        *(float4*)(wsm + i) = *(const float4*)(g_wk + i);
    __syncthreads();

    int pix = blockIdx.x * 128 + threadIdx.x;
    int b  = pix / HWv;
    int hw = pix % HWv;
    int h  = hw / Wv;
    int w  = hw % Wv;

    unsigned long long acc[14];
    #pragma unroll
    for (int j = 0; j < 14; j++) {
        int a = 2*j, c2 = 2*j + 1;
        float lo = (a  < 18) ? sem_b[a]  : ((a  < 27) ? m2_b[a  - 18] : 0.f);
        float hi = (c2 < 18) ? sem_b[c2] : ((c2 < 27) ? m2_b[c2 - 18] : 0.f);
        acc[j] = pack2(lo, hi);
    }

    #pragma unroll 1
    for (int k = 0; k < 9; k++) {
        int yy = h + k / 3 - 1, xx = w + k % 3 - 1;
        if ((unsigned)yy < Hv && (unsigned)xx < Wv) {
            const float* xp = input + (size_t)b*CINv*HWv + yy*Wv + xx;
            const float* wrow = wsm + k * 64 * 28;
            #pragma unroll 4
            for (int c = 0; c < 64; c++) {
                float x = xp[c * HWv];
                unsigned long long s2 = pack2(x, x);
                const ulonglong2* wp = (const ulonglong2*)(wrow + c * 28);
                #pragma unroll
                for (int j2 = 0; j2 < 7; j2++) {
                    ulonglong2 q = wp[j2];
                    ffma2(acc[2*j2],     s2, q.x);
                    ffma2(acc[2*j2 + 1], s2, q.y);
                }
            }
        }
    }
    float res[28];
    #pragma unroll
    for (int j = 0; j < 14; j++) { float2 t = unpack2(acc[j]); res[2*j] = t.x; res[2*j+1] = t.y; }

    float mv[9];
    #pragma unroll
    for (int k = 0; k < 9; k++) {
        int yy = h + k / 3 - 1, xx = w + k % 3 - 1;
        mv[k] = ((unsigned)yy < Hv && (unsigned)xx < Wv) ? mask[(size_t)b*HWv + yy*Wv + xx] : 0.f;
    }
    float ro[18];
    #pragma unroll
    for (int i = 0; i < 18; i++) {
        float s = reg_b[i];
        #pragma unroll
        for (int k = 0; k < 9; k++) s += mv[k] * __ldg(&reg_w[i*9 + k]);
        ro[i] = s;
    }
    float d1[9];
    #pragma unroll
    for (int j = 0; j < 9; j++) {
        float s = m1_b[j];
        #pragma unroll
        for (int k = 0; k < 9; k++) s += mv[k] * __ldg(&m1_w[j*9 + k]);
        d1[j] = 1.f / (1.f + __expf(-s));
    }

    const float* mb = mask + (size_t)b * HWv;
    float umsum = 0.f;
    #pragma unroll
    for (int g = 0; g < 2; g++) {
        #pragma unroll
        for (int k = 0; k < 9; k++) {
            float dy = g ? res[2*k]     : ro[2*k];
            float dx = g ? res[2*k + 1] : ro[2*k + 1];
            float py = dy + (float)h + (float)(k / 3 - 1);
            float px = dx + (float)w + (float)(k % 3 - 1);
            int idx = (((b*2 + g)*9) + k) * HWv + hw;
            g_py[idx] = py;
            g_px[idx] = px;
            g_dm[idx] = g ? (1.f / (1.f + __expf(-res[18 + k]))) : d1[k];

            float y0f = floorf(py), x0f = floorf(px);
            int y0 = (int)y0f, x0 = (int)x0f;
            float ly = py - y0f, lx = px - x0f;
            float v00 = ((unsigned)y0     < Hv && (unsigned)x0     < Wv) ? mb[y0*Wv + x0]         : 0.f;
            float v01 = ((unsigned)y0     < Hv && (unsigned)(x0+1) < Wv) ? mb[y0*Wv + x0 + 1]     : 0.f;
            float v10 = ((unsigned)(y0+1) < Hv && (unsigned)x0     < Wv) ? mb[(y0+1)*Wv + x0]     : 0.f;
            float v11 = ((unsigned)(y0+1) < Hv && (unsigned)(x0+1) < Wv) ? mb[(y0+1)*Wv + x0 + 1] : 0.f;
            umsum += (v00*(1.f-ly) + v10*ly)*(1.f-lx) + (v01*(1.f-ly) + v11*ly)*lx;
        }
    }
    out[(size_t)Bv*COUTv*HWv + (size_t)b*HWv + hw] = fminf(fmaxf(64.f * umsum, 0.f), 1.f);
}

// ---------------- fused gather + GEMM with double-buffered kk pipeline ----------------
// block = 256 thr (8 warps), tile 64o x 256px, thread tile 8o x 8px (32 f32x2 acc).
// Per iteration: prefetch slice kk+1 (W stage + warp-local params + gather ->
// buffer nxt), then fma on buffer cur. One __syncthreads per iteration; gather
// LDGs of kk+1 overlap fma of kk.
__global__ void __launch_bounds__(256, 2)
k_fused(const float* __restrict__ bias, float* __restrict__ out) {
    extern __shared__ float dsm[];
    float*  Wsm = dsm;                         // 2 x 2048 floats
    float*  Ssm = dsm + 4096;                  // 2 x 32*SSTR floats
    int4*   po  = (int4*)(dsm + 4096 + 2*32*SSTR);   // 2 x 256
    float4* pw  = (float4*)(po + 512);               // 2 x 256

    int t   = threadIdx.x;
    int w   = t >> 5, l = t & 31;
    int b   = blockIdx.x / (HWv / 256);
    int hw0 = (blockIdx.x % (HWv / 256)) * 256;
    int ob  = (t >> 5) << 3;   // out-channel base
    int ps  = t & 31;          // pixel-chunk selector

    unsigned long long acc[32];
    #pragma unroll
    for (int j = 0; j < 32; j++) acc[j] = 0ull;

    const float* xb = g_nhwc + ((size_t)b * HWv) * 64 + l;  // + g*32 added per kk

    // ---- prefetch helper (inlined twice via lambda) ----
    auto prep = [&](int buf, int kk) {
        // stage weights
        const float4* wsrc = (const float4*)(g_wt + kk * 2048);
        ((float4*)(Wsm + buf*2048))[t]       = wsrc[t];
        ((float4*)(Wsm + buf*2048))[t + 256] = wsrc[t + 256];
        // warp-local params: thread t = pixel 32w+l handles its own pixel
        {
            int gi = (b * 18 + kk) * HWv + hw0 + t;
            float py = g_py[gi], px = g_px[gi], dm = g_dm[gi];
            float y0f = floorf(py), x0f = floorf(px);
            int y0 = (int)y0f, x0 = (int)x0f;
            float ly = py - y0f, lx = px - x0f;
            bool vy0 = (unsigned)y0       < Hv;
            bool vy1 = (unsigned)(y0 + 1) < Hv;
            bool vx0 = (unsigned)x0       < Wv;
            bool vx1 = (unsigned)(x0 + 1) < Wv;
            float w00 = (vy0 && vx0) ? (1.f-ly)*(1.f-lx)*dm : 0.f;
            float w01 = (vy0 && vx1) ? (1.f-ly)*lx*dm       : 0.f;
            float w10 = (vy1 && vx0) ? ly*(1.f-lx)*dm       : 0.f;
            float w11 = (vy1 && vx1) ? ly*lx*dm             : 0.f;
            int yc0 = min(max(y0, 0), Hv-1),   yc1 = min(max(y0+1, 0), Hv-1);
            int xc0 = min(max(x0, 0), Wv-1),   xc1 = min(max(x0+1, 0), Wv-1);
            po[buf*256 + t] = make_int4((yc0*Wv + xc0)*64, (yc0*Wv + xc1)*64,
                                        (yc1*Wv + xc0)*64, (yc1*Wv + xc1)*64);
            pw[buf*256 + t] = make_float4(w00, w01, w10, w11);
        }
        __syncwarp();
        // gather: lane = channel l, warp w covers pixels [32w, 32w+32)
        const float* xg = xb + (kk / 9) * 32;
        float* srow = Ssm + buf*32*SSTR + l * SSTR + 32 * w;
        #pragma unroll
        for (int j = 0; j < 8; j++) {
            float v[4];
            #pragma unroll
            for (int e = 0; e < 4; e++) {
                int p = buf*256 + 32*w + 4*j + e;
                int4   o  = po[p];
                float4 wv = pw[p];
                v[e] = xg[o.x]*wv.x + xg[o.y]*wv.y + xg[o.z]*wv.z + xg[o.w]*wv.w;
            }
            *(float4*)(srow + 4*j) = make_float4(v[0], v[1], v[2], v[3]);
        }
    };

    prep(0, 0);
    __syncthreads();

    #pragma unroll 1
    for (int kk = 0; kk < 18; kk++) {
        int cur = kk & 1;
        if (kk < 17) prep(cur ^ 1, kk + 1);

        const float* Sc = Ssm + cur*32*SSTR;
        const float* Wc = Wsm + cur*2048;
        #pragma unroll 4
        for (int c = 0; c < 32; c++) {
            ulonglong2 s01 = *(const ulonglong2*)(Sc + c * SSTR + 4*ps);
            ulonglong2 s23 = *(const ulonglong2*)(Sc + c * SSTR + 128 + 4*ps);
            float4 w0 = *(const float4*)(Wc + c * 64 + ob);
            float4 w1 = *(const float4*)(Wc + c * 64 + ob + 4);
            float wa[8] = {w0.x, w0.y, w0.z, w0.w, w1.x, w1.y, w1.z, w1.w};
            #pragma unroll
            for (int e = 0; e < 8; e++) {
                unsigned long long w2 = pack2(wa[e], wa[e]);
                ffma2(acc[e*4 + 0], w2, s01.x);
                ffma2(acc[e*4 + 1], w2, s01.y);
                ffma2(acc[e*4 + 2], w2, s23.x);
                ffma2(acc[e*4 + 3], w2, s23.y);
            }
        }
        __syncthreads();
    }

    // epilogue: (acc + bias) * update_mask
    const float* umB = out + (size_t)Bv*COUTv*HWv + (size_t)b*HWv + hw0;
    float4 um0 = *(const float4*)(umB + 4*ps);
    float4 um1 = *(const float4*)(umB + 128 + 4*ps);
    #pragma unroll
    for (int e = 0; e < 8; e++) {
        float bv = bias[ob + e];
        float2 r0 = unpack2(acc[e*4 + 0]);
        float2 r1 = unpack2(acc[e*4 + 1]);
        float2 r2 = unpack2(acc[e*4 + 2]);
        float2 r3 = unpack2(acc[e*4 + 3]);
        float* op = out + ((size_t)b*COUTv + ob + e)*HWv + hw0;
        float4 o0 = {(r0.x + bv)*um0.x, (r0.y + bv)*um0.y,
                     (r1.x + bv)*um0.z, (r1.y + bv)*um0.w};
        float4 o1 = {(r2.x + bv)*um1.x, (r2.y + bv)*um1.y,
                     (r3.x + bv)*um1.z, (r3.y + bv)*um1.w};
        *(float4*)(op + 4*ps)       = o0;
        *(float4*)(op + 128 + 4*ps) = o1;
    }
}

// ---------------- launcher ----------------
extern "C" void kernel_launch(void* const* d_in, const int* in_sizes, int n_in,
                              void* d_out, int out_size) {
    const float* input  = (const float*)d_in[0];
    const float* mask   = (const float*)d_in[1];
    const float* weight = (const float*)d_in[2];
    const float* bias   = (const float*)d_in[3];
    const float* sem_w  = (const float*)d_in[4];
    const float* sem_b  = (const float*)d_in[5];
    const float* reg_w  = (const float*)d_in[6];
    const float* reg_b  = (const float*)d_in[7];
    const float* m1_w   = (const float*)d_in[8];
    const float* m1_b   = (const float*)d_in[9];
    const float* m2_w   = (const float*)d_in[10];
    const float* m2_b   = (const float*)d_in[11];
    float* out = (float*)d_out;

    const int fusedSmem = (4096 + 2*32*SSTR) * 4 + 512*16 + 512*16;  // ~97KB

    cudaFuncSetAttribute(k_offsets, cudaFuncAttributeMaxDynamicSharedMemorySize, KKv*64*28*4);
    cudaFuncSetAttribute(k_fused,   cudaFuncAttributeMaxDynamicSharedMemorySize, fusedSmem);

    k_transpose<<<dim3(Wv/32, Hv, Bv), 256>>>(input);
    k_prep<<<(Gv*KKv*CGv*COUTv + 255)/256, 256>>>(weight, sem_w, m2_w);
    k_offsets<<<(Bv*HWv)/128, 128, KKv*64*28*4>>>(input, mask, sem_b, reg_w, reg_b,
                                                  m1_w, m1_b, m2_b, out);
    k_fused<<<(Bv*HWv)/256, 256, fusedSmem>>>(bias, out);
}